// round 5
// baseline (speedup 1.0000x reference)
#include <cuda_runtime.h>

#define T    4
#define HH   64
#define HE   16
#define HD   128
#define KIN  145         // 2*HH + 1 + HE
#define KPAD 160         // KIN rounded to 32
#define NKIN 192
#define EPB  32          // edges per edge-block
#define ROWS 128         // EPB*T rows per block
#define STRIDE 132       // padded row length (floats) in A buffer
#define NPB  4
#define RPB  16
#define MAXN 20000
#define EPSF 1e-8f

typedef unsigned long long u64;

// Scratch (device globals — no allocation allowed)
__device__ float g_mi[MAXN * HD * T];   // segment-summed m_ij  [N,HD,T]
__device__ float g_agg[MAXN * 3 * T];   // coord aggregate      [N,3,T]
__device__ float g_cnt[MAXN];           // edge counts          [N]

__device__ __forceinline__ float silu_f(float v) {
    return v / (1.0f + __expf(-v));
}

// packed fp32x2 FMA: d = a*b + d  (Blackwell FFMA2)
#define FMA2(d, a, b) asm("fma.rn.f32x2 %0, %1, %2, %0;" : "+l"(d) : "l"(a), "l"(b))

__device__ __forceinline__ u64 pack2(float v) {
    u64 r; asm("mov.b64 %0, {%1, %1};" : "=l"(r) : "f"(v)); return r;
}
__device__ __forceinline__ u64 packab(float a, float b) {
    u64 r; asm("mov.b64 %0, {%1, %2};" : "=l"(r) : "f"(a), "f"(b)); return r;
}
__device__ __forceinline__ void unpack2(u64 v, float& lo, float& hi) {
    asm("mov.b64 {%0, %1}, %2;" : "=f"(lo), "=f"(hi) : "l"(v));
}

// ---------------------------------------------------------------------------
// Register-tiled GEMM phase over a 128-row x 128-col tile.
// Thread (ty 0..31, tx 0..7): rows 4ty..4ty+3, cols 16tx..16tx+15.
// Accumulators pack COLUMN pairs (w loads arrive as natural b64 pairs from
// smem, conflict-free); only the 4 a-values per k need duplication (8 MOV32,
// half of the 8x8 tile scheme). Per k-step: 32 FFMA2 + 5 LDS.128 + 8 MOV32.
// ---------------------------------------------------------------------------
template<int NCHUNK, int KLIM, bool ACT>
__device__ __forceinline__ void gemm_phase(
    const float* __restrict__ sA, float* __restrict__ sW,
    const float* __restrict__ gW, const float* __restrict__ gB,
    int tid, int tx, int ty, float (&out)[4][16])
{
    u64 acc[4][8];
    {
        float4 b0 = *(const float4*)(gB + 16 * tx);
        float4 b1 = *(const float4*)(gB + 16 * tx + 4);
        float4 b2 = *(const float4*)(gB + 16 * tx + 8);
        float4 b3 = *(const float4*)(gB + 16 * tx + 12);
        u64 bp[8] = {packab(b0.x, b0.y), packab(b0.z, b0.w),
                     packab(b1.x, b1.y), packab(b1.z, b1.w),
                     packab(b2.x, b2.y), packab(b2.z, b2.w),
                     packab(b3.x, b3.y), packab(b3.z, b3.w)};
#pragma unroll
        for (int r = 0; r < 4; r++)
#pragma unroll
            for (int cp = 0; cp < 8; cp++) acc[r][cp] = bp[cp];
    }

    // W chunk: 32 k x 128 cols; per-thread 4 float4 prefetch regs
    float4 pre[4];
#pragma unroll
    for (int i = 0; i < 4; i++) {
        int off = i * 1024 + tid * 4;
        int kg = off >> 7;
        pre[i] = (kg < KLIM) ? *(const float4*)(gW + kg * HD + (off & 127))
                             : make_float4(0.f, 0.f, 0.f, 0.f);
    }

#pragma unroll 1
    for (int kc = 0; kc < NCHUNK; kc++) {
        __syncthreads();                       // prev chunk consumers done
#pragma unroll
        for (int i = 0; i < 4; i++)
            *(float4*)(sW + i * 1024 + tid * 4) = pre[i];
        __syncthreads();
        if (kc + 1 < NCHUNK) {
#pragma unroll
            for (int i = 0; i < 4; i++) {
                int off = i * 1024 + tid * 4;
                int kg = (kc + 1) * 32 + (off >> 7);
                pre[i] = (kg < KLIM) ? *(const float4*)(gW + kg * HD + (off & 127))
                                     : make_float4(0.f, 0.f, 0.f, 0.f);
            }
        }
        const float* ap = sA + (kc * 32) * STRIDE + ty * 4;
#pragma unroll 8
        for (int kk = 0; kk < 32; kk++) {
            float4 a4 = *(const float4*)(ap);
            ap += STRIDE;
            const float* wp = sW + kk * HD + 16 * tx;
            ulonglong2 w01 = *(const ulonglong2*)(wp);
            ulonglong2 w23 = *(const ulonglong2*)(wp + 4);
            ulonglong2 w45 = *(const ulonglong2*)(wp + 8);
            ulonglong2 w67 = *(const ulonglong2*)(wp + 12);
            u64 ad[4] = {pack2(a4.x), pack2(a4.y), pack2(a4.z), pack2(a4.w)};
#pragma unroll
            for (int r = 0; r < 4; r++) {
                FMA2(acc[r][0], ad[r], w01.x);
                FMA2(acc[r][1], ad[r], w01.y);
                FMA2(acc[r][2], ad[r], w23.x);
                FMA2(acc[r][3], ad[r], w23.y);
                FMA2(acc[r][4], ad[r], w45.x);
                FMA2(acc[r][5], ad[r], w45.y);
                FMA2(acc[r][6], ad[r], w67.x);
                FMA2(acc[r][7], ad[r], w67.y);
            }
        }
    }

#pragma unroll
    for (int r = 0; r < 4; r++)
#pragma unroll
        for (int cp = 0; cp < 8; cp++) {
            float lo, hi; unpack2(acc[r][cp], lo, hi);
            out[r][2 * cp]     = ACT ? silu_f(lo) : lo;
            out[r][2 * cp + 1] = ACT ? silu_f(hi) : hi;
        }
}

__global__ void zero_kernel(int n) {
    int stride = gridDim.x * blockDim.x;
    int base = blockIdx.x * blockDim.x + threadIdx.x;
    for (int i = base; i < n * HD * T; i += stride) g_mi[i] = 0.0f;
    for (int i = base; i < n * 3 * T;  i += stride) g_agg[i] = 0.0f;
    for (int i = base; i < n;          i += stride) g_cnt[i] = 0.0f;
}

__global__ __launch_bounds__(256, 2) void edge_kernel(
    const float* __restrict__ x, const float* __restrict__ h,
    const int* __restrict__ ei, const float* __restrict__ ea,
    const float* __restrict__ w1, const float* __restrict__ b1,
    const float* __restrict__ w2, const float* __restrict__ b2,
    const float* __restrict__ cw1, const float* __restrict__ cb1,
    const float* __restrict__ cw2, const float* __restrict__ cb2,
    int E)
{
    extern __shared__ float sm[];
    float* s_buf = sm;                         // KPAD*STRIDE floats (A/mid/m_ij)
    float* s_w   = sm + KPAD * STRIDE;         // 32*HD floats
    float* s_part = s_buf;                     // 8*ROWS, overlays s_buf late

    __shared__ int   s_rown[EPB], s_coln[EPB];
    __shared__ float s_xij[EPB][3][T];
    __shared__ float s_n2[ROWS];

    const int tid = threadIdx.x;
    const int tx  = tid & 7;                   // col group: cols 16tx..16tx+15
    const int ty  = tid >> 3;                  // row group: rows 4ty..4ty+3 (edge ty)
    const int e0  = blockIdx.x * EPB;

    if (tid < EPB) {
        int eg = e0 + tid;
        if (eg >= E) eg = E - 1;
        s_rown[tid] = ei[eg];
        s_coln[tid] = ei[E + eg];
    }
    __syncthreads();

    // ---- gather: h[row] (ch 0..63), h[col] (64..127) — float4 over t ----
#pragma unroll
    for (int it = 0; it < 16; it++) {
        int idx  = it * 256 + tid;             // 4096 float4 items
        int k    = idx & 63;
        int e    = (idx >> 6) & 31;
        int side = idx >> 11;
        int node = side ? s_coln[e] : s_rown[e];
        float4 v = *(const float4*)(h + ((size_t)node * HH + k) * T);
        *(float4*)(s_buf + (side * HH + k) * STRIDE + e * 4) = v;
    }
    // ---- edge_attr: ch 129..144 ----
#pragma unroll
    for (int it = 0; it < 2; it++) {
        int idx = it * 256 + tid;              // 512 items
        int k = idx & 15;
        int e = idx >> 4;
        int eg = e0 + e; if (eg >= E) eg = E - 1;
        float4 v = *(const float4*)(ea + ((size_t)eg * HE + k) * T);
        *(float4*)(s_buf + (129 + k) * STRIDE + e * 4) = v;
    }
    // ---- zero pad channels 145..159 ----
    for (int i = tid; i < 15 * 32; i += 256) {
        int k = 145 + (i >> 5);
        *(float4*)(s_buf + k * STRIDE + (i & 31) * 4) = make_float4(0.f, 0.f, 0.f, 0.f);
    }
    // ---- x_ij, n2 (ch 128) ----
    if (tid < ROWS) {
        int e = tid >> 2, t = tid & 3;
        int rn = s_rown[e], cn = s_coln[e];
        float n2 = 0.f;
#pragma unroll
        for (int d = 0; d < 3; d++) {
            float v = x[((size_t)rn * 3 + d) * T + t] - x[((size_t)cn * 3 + d) * T + t];
            s_xij[e][d][t] = v;
            n2 += v * v;
        }
        s_buf[128 * STRIDE + tid] = n2;
        s_n2[tid] = n2;
    }
    // (gemm_phase's first __syncthreads covers gather->compute ordering)

    // ---- layer 1: silu(A @ W1 + b1) ----
    float o1[4][16];
    gemm_phase<5, KIN, true>(s_buf, s_w, w1, b1, tid, tx, ty, o1);

    __syncthreads();                           // all A reads done
#pragma unroll
    for (int c = 0; c < 16; c++) {
        int col = 16 * tx + c;
        *(float4*)(s_buf + col * STRIDE + ty * 4) =
            make_float4(o1[0][c], o1[1][c], o1[2][c], o1[3][c]);
    }
    __syncthreads();

    // ---- layer 2: m_ij = silu(mid @ W2 + b2) ----
    float o2[4][16];
    gemm_phase<4, HD, true>(s_buf, s_w, w2, b2, tid, tx, ty, o2);

    // ---- scatter m_i: thread owns edge ty, t = rows 0..3 of its tile ----
    if (e0 + ty < E) {
        int node = s_rown[ty];
#pragma unroll
        for (int c = 0; c < 16; c++) {
            int col = 16 * tx + c;
            float* p = &g_mi[((size_t)node * HD + col) * T];
            asm volatile("red.global.add.v4.f32 [%0], {%1,%2,%3,%4};"
                         :: "l"(p), "f"(o2[0][c]), "f"(o2[1][c]),
                            "f"(o2[2][c]), "f"(o2[3][c])
                         : "memory");
        }
    }

    // ---- m_ij -> smem for coord MLP ----
    __syncthreads();
#pragma unroll
    for (int c = 0; c < 16; c++) {
        int col = 16 * tx + c;
        *(float4*)(s_buf + col * STRIDE + ty * 4) =
            make_float4(o2[0][c], o2[1][c], o2[2][c], o2[3][c]);
    }
    __syncthreads();

    // ---- coord layer 1: silu(m_ij @ cw1 + cb1) ----
    float o3[4][16];
    gemm_phase<4, HD, true>(s_buf, s_w, cw1, cb1, tid, tx, ty, o3);

    // ---- coord projection to 1: partials over this thread's 16 cols ----
    {
        float4 c0 = *(const float4*)(cw2 + 16 * tx);
        float4 c1 = *(const float4*)(cw2 + 16 * tx + 4);
        float4 c2 = *(const float4*)(cw2 + 16 * tx + 8);
        float4 c3 = *(const float4*)(cw2 + 16 * tx + 12);
        float cw[16] = {c0.x, c0.y, c0.z, c0.w, c1.x, c1.y, c1.z, c1.w,
                        c2.x, c2.y, c2.z, c2.w, c3.x, c3.y, c3.z, c3.w};
        float p[4];
#pragma unroll
        for (int r = 0; r < 4; r++) {
            float s = 0.f;
#pragma unroll
            for (int c = 0; c < 16; c++) s += o3[r][c] * cw[c];
            p[r] = s;
        }
        __syncthreads();                       // s_buf reads (GEMM3) done
        *(float4*)(s_part + tx * ROWS + ty * 4) = make_float4(p[0], p[1], p[2], p[3]);
    }
    __syncthreads();

    if (tid < ROWS) {
        float cval = cb2[0];
#pragma unroll
        for (int q = 0; q < 8; q++) cval += s_part[q * ROWS + tid];
        cval /= (sqrtf(s_n2[tid] + EPSF) + 1.0f);
        int e = tid >> 2, t = tid & 3;
        if (e0 + e < E) {
            int node = s_rown[e];
#pragma unroll
            for (int d = 0; d < 3; d++)
                atomicAdd(&g_agg[((size_t)node * 3 + d) * T + t], cval * s_xij[e][d][t]);
            if (t == 0) atomicAdd(&g_cnt[node], 1.0f);
        }
    }
}

// ---------------------------------------------------------------------------
// Node kernel (unchanged from round 3)
// ---------------------------------------------------------------------------
__global__ __launch_bounds__(128) void node_kernel(
    const float* __restrict__ x, const float* __restrict__ h,
    const float* __restrict__ nw1, const float* __restrict__ nb1,
    const float* __restrict__ nw2, const float* __restrict__ nb2,
    float* __restrict__ out_x, float* __restrict__ out_h, int N)
{
    __shared__ __align__(16) float s_in[NKIN][RPB];
    __shared__ __align__(16) float s_a[HD][RPB];

    const int tid = threadIdx.x;
    const int n0  = blockIdx.x * NPB;

    if (tid < NPB * 12) {
        int n = n0 + tid / 12;
        if (n < N) {
            int rem = tid % 12, d = rem >> 2, t = rem & 3;
            float cv = fmaxf(g_cnt[n], 1.0f);
            int off = (n * 3 + d) * T + t;
            out_x[off] = x[off] + g_agg[off] / cv;
        }
    }

#pragma unroll
    for (int it = 0; it < 24; it++) {
        int idx = it * 128 + tid;
        int k = idx >> 4, i = idx & 15;
        int n = n0 + (i >> 2), t = i & 3;
        int nn = (n < N) ? n : 0;
        float v = (k < HH) ? h[(nn * HH + k) * T + t]
                           : g_mi[(nn * HD + (k - HH)) * T + t];
        s_in[k][i] = v;
    }
    __syncthreads();

    // layer 1: 192 -> 128, silu
    {
        u64 acc[8];
        u64 bp = pack2(nb1[tid]);
#pragma unroll
        for (int i = 0; i < 8; i++) acc[i] = bp;
#pragma unroll 4
        for (int k = 0; k < NKIN; k++) {
            u64 wp = pack2(nw1[k * HD + tid]);
            const ulonglong2* pp = reinterpret_cast<const ulonglong2*>(s_in[k]);
            ulonglong2 p0 = pp[0], p1 = pp[1];
            FMA2(acc[0], p0.x, wp); FMA2(acc[1], p0.y, wp);
            FMA2(acc[2], p1.x, wp); FMA2(acc[3], p1.y, wp);
            ulonglong2 p2 = pp[2], p3 = pp[3];
            FMA2(acc[4], p2.x, wp); FMA2(acc[5], p2.y, wp);
            FMA2(acc[6], p3.x, wp); FMA2(acc[7], p3.y, wp);
        }
#pragma unroll
        for (int i = 0; i < 8; i++) {
            float lo, hi; unpack2(acc[i], lo, hi);
            s_a[tid][2 * i]     = silu_f(lo);
            s_a[tid][2 * i + 1] = silu_f(hi);
        }
    }
    __syncthreads();

    // layer 2: 128 -> 64, linear
    if (tid < HH) {
        u64 acc[8];
        u64 bp = pack2(nb2[tid]);
#pragma unroll
        for (int i = 0; i < 8; i++) acc[i] = bp;
#pragma unroll 4
        for (int k = 0; k < HD; k++) {
            u64 wp = pack2(nw2[k * HH + tid]);
            const ulonglong2* pp = reinterpret_cast<const ulonglong2*>(s_a[k]);
            ulonglong2 p0 = pp[0], p1 = pp[1];
            FMA2(acc[0], p0.x, wp); FMA2(acc[1], p0.y, wp);
            FMA2(acc[2], p1.x, wp); FMA2(acc[3], p1.y, wp);
            ulonglong2 p2 = pp[2], p3 = pp[3];
            FMA2(acc[4], p2.x, wp); FMA2(acc[5], p2.y, wp);
            FMA2(acc[6], p3.x, wp); FMA2(acc[7], p3.y, wp);
        }
#pragma unroll
        for (int nl = 0; nl < NPB; nl++) {
            int n = n0 + nl;
            if (n < N) {
                float4 o;
                unpack2(acc[2 * nl],     o.x, o.y);
                unpack2(acc[2 * nl + 1], o.z, o.w);
                *reinterpret_cast<float4*>(&out_h[(n * HH + tid) * T]) = o;
            }
        }
    }
}

extern "C" void kernel_launch(void* const* d_in, const int* in_sizes, int n_in,
                              void* d_out, int out_size)
{
    const float* x   = (const float*)d_in[0];
    const float* h   = (const float*)d_in[1];
    const int*   ei  = (const int*)  d_in[2];
    const float* ea  = (const float*)d_in[3];
    const float* ew1 = (const float*)d_in[5];
    const float* eb1 = (const float*)d_in[6];
    const float* ew2 = (const float*)d_in[7];
    const float* eb2 = (const float*)d_in[8];
    const float* cw1 = (const float*)d_in[9];
    const float* cb1 = (const float*)d_in[10];
    const float* cw2 = (const float*)d_in[11];
    const float* cb2 = (const float*)d_in[12];
    const float* nw1 = (const float*)d_in[13];
    const float* nb1 = (const float*)d_in[14];
    const float* nw2 = (const float*)d_in[15];
    const float* nb2 = (const float*)d_in[16];

    int N = in_sizes[0] / (3 * T);
    int E = in_sizes[3] / (HE * T);

    float* out_x = (float*)d_out;
    float* out_h = out_x + (size_t)N * 3 * T;

    const int smem_bytes = (KPAD * STRIDE + 32 * HD) * sizeof(float);
    cudaFuncSetAttribute(edge_kernel, cudaFuncAttributeMaxDynamicSharedMemorySize,
                         smem_bytes);

    zero_kernel<<<2048, 256>>>(N);
    edge_kernel<<<(E + EPB - 1) / EPB, 256, smem_bytes>>>(
        x, h, ei, ea, ew1, eb1, ew2, eb2, cw1, cb1, cw2, cb2, E);
    node_kernel<<<(N + NPB - 1) / NPB, 128>>>(x, h, nw1, nb1, nw2, nb2,
                                              out_x, out_h, N);
}

// round 6
// speedup vs baseline: 2.3268x; 2.3268x over previous
#include <cuda_runtime.h>

#define T    4
#define HH   64
#define HE   16
#define HD   128
#define KIN  145         // 2*HH + 1 + HE
#define KPAD 160         // KIN rounded to 32
#define NKIN 192
#define EPB  32          // edges per edge-block
#define ROWS 128         // EPB*T rows per block
#define STRIDE 132       // padded row length (floats) in A buffer
#define KCHUNK 16
#define NPB  4
#define RPB  16
#define MAXN 20000
#define EPSF 1e-8f

typedef unsigned long long u64;

// Scratch (device globals — no allocation allowed)
__device__ float g_mi[MAXN * HD * T];   // segment-summed m_ij  [N,HD,T]
__device__ float g_agg[MAXN * 3 * T];   // coord aggregate      [N,3,T]
__device__ float g_cnt[MAXN];           // edge counts          [N]

__device__ __forceinline__ float silu_f(float v) {
    return v / (1.0f + __expf(-v));
}

// packed fp32x2 FMA: d = a*b + d  (Blackwell FFMA2)
#define FMA2(d, a, b) asm("fma.rn.f32x2 %0, %1, %2, %0;" : "+l"(d) : "l"(a), "l"(b))

__device__ __forceinline__ u64 packab(float a, float b) {
    u64 r; asm("mov.b64 %0, {%1, %2};" : "=l"(r) : "f"(a), "f"(b)); return r;
}
__device__ __forceinline__ u64 pack2(float v) { return packab(v, v); }
__device__ __forceinline__ void unpack2(u64 v, float& lo, float& hi) {
    asm("mov.b64 {%0, %1}, %2;" : "=f"(lo), "=f"(hi) : "l"(v));
}

// ---------------------------------------------------------------------------
// Register-tiled GEMM phase over a 128-row x 128-col tile, diagonal-pair form.
// Thread (ty 0..15, tx 0..15): rows 8ty..8ty+7, cols {4tx..4tx+3, 64+4tx..+3}.
// acc packs DIAGONAL element pairs: one FFMA2 on a natural row-pair (a2p,a2p+1)
// and a natural col-pair (w2q,w2q+1) accumulates (D[2p][2q], D[2p+1][2q+1]);
// the anti-diagonal uses a pre-swapped W copy (w2q+1,w2q) staged in smem.
// Inner loop per k: 32 FFMA2 + 6 LDS.128, ZERO pack MOVs.
// out[r][c]: c 0..3 -> col 4tx+c ; c 4..7 -> col 60+4tx+c  (same as round 3).
// ---------------------------------------------------------------------------
template<int NCHUNK, int KLIM, bool ACT>
__device__ __forceinline__ void gemm_phase(
    const float* __restrict__ sA, float* __restrict__ sW,
    const float* __restrict__ gW, const float* __restrict__ gB,
    int tid, int tx, int ty, float (&out)[8][8])
{
    float* sWs = sW + KCHUNK * HD;             // swapped-pair copy

    u64 accD[4][4], accA[4][4];
    {
        float4 bA = *(const float4*)(gB + 4 * tx);
        float4 bB = *(const float4*)(gB + 64 + 4 * tx);
        u64 d0 = packab(bA.x, bA.y), a0 = packab(bA.y, bA.x);
        u64 d1 = packab(bA.z, bA.w), a1 = packab(bA.w, bA.z);
        u64 d2 = packab(bB.x, bB.y), a2 = packab(bB.y, bB.x);
        u64 d3 = packab(bB.z, bB.w), a3 = packab(bB.w, bB.z);
#pragma unroll
        for (int p = 0; p < 4; p++) {
            accD[p][0] = d0; accD[p][1] = d1; accD[p][2] = d2; accD[p][3] = d3;
            accA[p][0] = a0; accA[p][1] = a1; accA[p][2] = a2; accA[p][3] = a3;
        }
    }

    // W chunk: KCHUNK(16) k x 128 cols; per-thread 2 float4 prefetch regs
    float4 pre[2];
#pragma unroll
    for (int i = 0; i < 2; i++) {
        int off = i * 1024 + tid * 4;
        int kg = off >> 7;
        pre[i] = (kg < KLIM) ? *(const float4*)(gW + kg * HD + (off & 127))
                             : make_float4(0.f, 0.f, 0.f, 0.f);
    }

#pragma unroll 1
    for (int kc = 0; kc < NCHUNK; kc++) {
        __syncthreads();                       // prev chunk consumers done
#pragma unroll
        for (int i = 0; i < 2; i++) {
            int off = i * 1024 + tid * 4;      // == kg*HD + col (HD==128)
            float4 v = pre[i];
            *(float4*)(sW + off)  = v;
            *(float4*)(sWs + off) = make_float4(v.y, v.x, v.w, v.z);
        }
        __syncthreads();
        if (kc + 1 < NCHUNK) {
#pragma unroll
            for (int i = 0; i < 2; i++) {
                int off = i * 1024 + tid * 4;
                int kg = (kc + 1) * KCHUNK + (off >> 7);
                pre[i] = (kg < KLIM) ? *(const float4*)(gW + kg * HD + (off & 127))
                                     : make_float4(0.f, 0.f, 0.f, 0.f);
            }
        }
        const float* ap = sA + (kc * KCHUNK) * STRIDE + ty * 8;
#pragma unroll
        for (int kk = 0; kk < KCHUNK; kk++) {
            ulonglong2 a01 = *(const ulonglong2*)(ap);
            ulonglong2 a23 = *(const ulonglong2*)(ap + 4);
            ap += STRIDE;
            const float* wn = sW  + kk * HD + 4 * tx;
            const float* ws = sWs + kk * HD + 4 * tx;
            ulonglong2 wnA = *(const ulonglong2*)(wn);
            ulonglong2 wnB = *(const ulonglong2*)(wn + 64);
            ulonglong2 wsA = *(const ulonglong2*)(ws);
            ulonglong2 wsB = *(const ulonglong2*)(ws + 64);
            u64 av[4] = {a01.x, a01.y, a23.x, a23.y};
#pragma unroll
            for (int p = 0; p < 4; p++) {
                FMA2(accD[p][0], av[p], wnA.x);
                FMA2(accD[p][1], av[p], wnA.y);
                FMA2(accD[p][2], av[p], wnB.x);
                FMA2(accD[p][3], av[p], wnB.y);
                FMA2(accA[p][0], av[p], wsA.x);
                FMA2(accA[p][1], av[p], wsA.y);
                FMA2(accA[p][2], av[p], wsB.x);
                FMA2(accA[p][3], av[p], wsB.y);
            }
        }
    }

#pragma unroll
    for (int p = 0; p < 4; p++)
#pragma unroll
        for (int q = 0; q < 4; q++) {
            float dlo, dhi, alo, ahi;
            unpack2(accD[p][q], dlo, dhi);
            unpack2(accA[p][q], alo, ahi);
            out[2 * p][2 * q]         = ACT ? silu_f(dlo) : dlo;
            out[2 * p + 1][2 * q + 1] = ACT ? silu_f(dhi) : dhi;
            out[2 * p][2 * q + 1]     = ACT ? silu_f(alo) : alo;
            out[2 * p + 1][2 * q]     = ACT ? silu_f(ahi) : ahi;
        }
}

__global__ void zero_kernel(int n) {
    int stride = gridDim.x * blockDim.x;
    int base = blockIdx.x * blockDim.x + threadIdx.x;
    for (int i = base; i < n * HD * T; i += stride) g_mi[i] = 0.0f;
    for (int i = base; i < n * 3 * T;  i += stride) g_agg[i] = 0.0f;
    for (int i = base; i < n;          i += stride) g_cnt[i] = 0.0f;
}

__global__ __launch_bounds__(256, 2) void edge_kernel(
    const float* __restrict__ x, const float* __restrict__ h,
    const int* __restrict__ ei, const float* __restrict__ ea,
    const float* __restrict__ w1, const float* __restrict__ b1,
    const float* __restrict__ w2, const float* __restrict__ b2,
    const float* __restrict__ cw1, const float* __restrict__ cb1,
    const float* __restrict__ cw2, const float* __restrict__ cb2,
    int E)
{
    extern __shared__ float sm[];
    float* s_buf = sm;                         // KPAD*STRIDE floats (A/mid/m_ij)
    float* s_w   = sm + KPAD * STRIDE;         // 2*KCHUNK*HD floats (W + swapped W)
    float* s_part = s_buf;                     // 16*ROWS, overlays s_buf late

    __shared__ int   s_rown[EPB], s_coln[EPB];
    __shared__ float s_xij[EPB][3][T];
    __shared__ float s_n2[ROWS];

    const int tid = threadIdx.x;
    const int tx  = tid & 15;
    const int ty  = tid >> 4;
    const int e0  = blockIdx.x * EPB;

    if (tid < EPB) {
        int eg = e0 + tid;
        if (eg >= E) eg = E - 1;
        s_rown[tid] = ei[eg];
        s_coln[tid] = ei[E + eg];
    }
    __syncthreads();

    // ---- gather: h[row] (ch 0..63), h[col] (64..127) — float4 over t ----
#pragma unroll
    for (int it = 0; it < 16; it++) {
        int idx  = it * 256 + tid;             // 4096 float4 items
        int k    = idx & 63;
        int e    = (idx >> 6) & 31;
        int side = idx >> 11;
        int node = side ? s_coln[e] : s_rown[e];
        float4 v = *(const float4*)(h + ((size_t)node * HH + k) * T);
        *(float4*)(s_buf + (side * HH + k) * STRIDE + e * 4) = v;
    }
    // ---- edge_attr: ch 129..144 ----
#pragma unroll
    for (int it = 0; it < 2; it++) {
        int idx = it * 256 + tid;              // 512 items
        int k = idx & 15;
        int e = idx >> 4;
        int eg = e0 + e; if (eg >= E) eg = E - 1;
        float4 v = *(const float4*)(ea + ((size_t)eg * HE + k) * T);
        *(float4*)(s_buf + (129 + k) * STRIDE + e * 4) = v;
    }
    // ---- zero pad channels 145..159 ----
    for (int i = tid; i < 15 * 32; i += 256) {
        int k = 145 + (i >> 5);
        *(float4*)(s_buf + k * STRIDE + (i & 31) * 4) = make_float4(0.f, 0.f, 0.f, 0.f);
    }
    // ---- x_ij, n2 (ch 128) ----
    if (tid < ROWS) {
        int e = tid >> 2, t = tid & 3;
        int rn = s_rown[e], cn = s_coln[e];
        float n2 = 0.f;
#pragma unroll
        for (int d = 0; d < 3; d++) {
            float v = x[((size_t)rn * 3 + d) * T + t] - x[((size_t)cn * 3 + d) * T + t];
            s_xij[e][d][t] = v;
            n2 += v * v;
        }
        s_buf[128 * STRIDE + tid] = n2;
        s_n2[tid] = n2;
    }
    // (gemm_phase's first __syncthreads covers gather->compute ordering)

    // ---- layer 1: silu(A @ W1 + b1) ----
    float o1[8][8];
    gemm_phase<KPAD / KCHUNK, KIN, true>(s_buf, s_w, w1, b1, tid, tx, ty, o1);

    __syncthreads();                           // all A reads done
#pragma unroll
    for (int c = 0; c < 8; c++) {
        int col = (c < 4) ? 4 * tx + c : 60 + 4 * tx + c;
        *(float4*)(s_buf + col * STRIDE + ty * 8) =
            make_float4(o1[0][c], o1[1][c], o1[2][c], o1[3][c]);
        *(float4*)(s_buf + col * STRIDE + ty * 8 + 4) =
            make_float4(o1[4][c], o1[5][c], o1[6][c], o1[7][c]);
    }
    __syncthreads();

    // ---- layer 2: m_ij = silu(mid @ W2 + b2) ----
    float o2[8][8];
    gemm_phase<HD / KCHUNK, HD, true>(s_buf, s_w, w2, b2, tid, tx, ty, o2);

    // ---- scatter m_i ----
#pragma unroll
    for (int eh = 0; eh < 2; eh++) {
        int el = 2 * ty + eh;
        if (e0 + el < E) {
            int node = s_rown[el];
#pragma unroll
            for (int c = 0; c < 8; c++) {
                int col = (c < 4) ? 4 * tx + c : 60 + 4 * tx + c;
                float* p = &g_mi[((size_t)node * HD + col) * T];
                asm volatile("red.global.add.v4.f32 [%0], {%1,%2,%3,%4};"
                             :: "l"(p), "f"(o2[eh * 4 + 0][c]), "f"(o2[eh * 4 + 1][c]),
                                "f"(o2[eh * 4 + 2][c]), "f"(o2[eh * 4 + 3][c])
                             : "memory");
            }
        }
    }

    // ---- m_ij -> smem for coord MLP ----
    __syncthreads();
#pragma unroll
    for (int c = 0; c < 8; c++) {
        int col = (c < 4) ? 4 * tx + c : 60 + 4 * tx + c;
        *(float4*)(s_buf + col * STRIDE + ty * 8) =
            make_float4(o2[0][c], o2[1][c], o2[2][c], o2[3][c]);
        *(float4*)(s_buf + col * STRIDE + ty * 8 + 4) =
            make_float4(o2[4][c], o2[5][c], o2[6][c], o2[7][c]);
    }
    __syncthreads();

    // ---- coord layer 1: silu(m_ij @ cw1 + cb1) ----
    float o3[8][8];
    gemm_phase<HD / KCHUNK, HD, true>(s_buf, s_w, cw1, cb1, tid, tx, ty, o3);

    // ---- coord projection to 1: partials ----
    {
        float4 c2a = *(const float4*)(cw2 + 4 * tx);
        float4 c2b = *(const float4*)(cw2 + 64 + 4 * tx);
        float cw[8] = {c2a.x, c2a.y, c2a.z, c2a.w, c2b.x, c2b.y, c2b.z, c2b.w};
        float p[8];
#pragma unroll
        for (int r = 0; r < 8; r++) {
            float s = 0.f;
#pragma unroll
            for (int c = 0; c < 8; c++) s += o3[r][c] * cw[c];
            p[r] = s;
        }
        __syncthreads();                       // s_buf reads (GEMM3) done
        *(float4*)(s_part + tx * ROWS + ty * 8) = make_float4(p[0], p[1], p[2], p[3]);
        *(float4*)(s_part + tx * ROWS + ty * 8 + 4) = make_float4(p[4], p[5], p[6], p[7]);
    }
    __syncthreads();

    if (tid < ROWS) {
        float cval = cb2[0];
#pragma unroll
        for (int q = 0; q < 16; q++) cval += s_part[q * ROWS + tid];
        cval /= (sqrtf(s_n2[tid] + EPSF) + 1.0f);
        int e = tid >> 2, t = tid & 3;
        if (e0 + e < E) {
            int node = s_rown[e];
#pragma unroll
            for (int d = 0; d < 3; d++)
                atomicAdd(&g_agg[((size_t)node * 3 + d) * T + t], cval * s_xij[e][d][t]);
            if (t == 0) atomicAdd(&g_cnt[node], 1.0f);
        }
    }
}

// ---------------------------------------------------------------------------
// Node kernel (unchanged from round 3)
// ---------------------------------------------------------------------------
__global__ __launch_bounds__(128) void node_kernel(
    const float* __restrict__ x, const float* __restrict__ h,
    const float* __restrict__ nw1, const float* __restrict__ nb1,
    const float* __restrict__ nw2, const float* __restrict__ nb2,
    float* __restrict__ out_x, float* __restrict__ out_h, int N)
{
    __shared__ __align__(16) float s_in[NKIN][RPB];
    __shared__ __align__(16) float s_a[HD][RPB];

    const int tid = threadIdx.x;
    const int n0  = blockIdx.x * NPB;

    if (tid < NPB * 12) {
        int n = n0 + tid / 12;
        if (n < N) {
            int rem = tid % 12, d = rem >> 2, t = rem & 3;
            float cv = fmaxf(g_cnt[n], 1.0f);
            int off = (n * 3 + d) * T + t;
            out_x[off] = x[off] + g_agg[off] / cv;
        }
    }

#pragma unroll
    for (int it = 0; it < 24; it++) {
        int idx = it * 128 + tid;
        int k = idx >> 4, i = idx & 15;
        int n = n0 + (i >> 2), t = i & 3;
        int nn = (n < N) ? n : 0;
        float v = (k < HH) ? h[(nn * HH + k) * T + t]
                           : g_mi[(nn * HD + (k - HH)) * T + t];
        s_in[k][i] = v;
    }
    __syncthreads();

    // layer 1: 192 -> 128, silu
    {
        u64 acc[8];
        u64 bp = pack2(nb1[tid]);
#pragma unroll
        for (int i = 0; i < 8; i++) acc[i] = bp;
#pragma unroll 4
        for (int k = 0; k < NKIN; k++) {
            u64 wp = pack2(nw1[k * HD + tid]);
            const ulonglong2* pp = reinterpret_cast<const ulonglong2*>(s_in[k]);
            ulonglong2 p0 = pp[0], p1 = pp[1];
            FMA2(acc[0], p0.x, wp); FMA2(acc[1], p0.y, wp);
            FMA2(acc[2], p1.x, wp); FMA2(acc[3], p1.y, wp);
            ulonglong2 p2 = pp[2], p3 = pp[3];
            FMA2(acc[4], p2.x, wp); FMA2(acc[5], p2.y, wp);
            FMA2(acc[6], p3.x, wp); FMA2(acc[7], p3.y, wp);
        }
#pragma unroll
        for (int i = 0; i < 8; i++) {
            float lo, hi; unpack2(acc[i], lo, hi);
            s_a[tid][2 * i]     = silu_f(lo);
            s_a[tid][2 * i + 1] = silu_f(hi);
        }
    }
    __syncthreads();

    // layer 2: 128 -> 64, linear
    if (tid < HH) {
        u64 acc[8];
        u64 bp = pack2(nb2[tid]);
#pragma unroll
        for (int i = 0; i < 8; i++) acc[i] = bp;
#pragma unroll 4
        for (int k = 0; k < HD; k++) {
            u64 wp = pack2(nw2[k * HH + tid]);
            const ulonglong2* pp = reinterpret_cast<const ulonglong2*>(s_a[k]);
            ulonglong2 p0 = pp[0], p1 = pp[1];
            FMA2(acc[0], p0.x, wp); FMA2(acc[1], p0.y, wp);
            FMA2(acc[2], p1.x, wp); FMA2(acc[3], p1.y, wp);
            ulonglong2 p2 = pp[2], p3 = pp[3];
            FMA2(acc[4], p2.x, wp); FMA2(acc[5], p2.y, wp);
            FMA2(acc[6], p3.x, wp); FMA2(acc[7], p3.y, wp);
        }
#pragma unroll
        for (int nl = 0; nl < NPB; nl++) {
            int n = n0 + nl;
            if (n < N) {
                float4 o;
                unpack2(acc[2 * nl],     o.x, o.y);
                unpack2(acc[2 * nl + 1], o.z, o.w);
                *reinterpret_cast<float4*>(&out_h[(n * HH + tid) * T]) = o;
            }
        }
    }
}

extern "C" void kernel_launch(void* const* d_in, const int* in_sizes, int n_in,
                              void* d_out, int out_size)
{
    const float* x   = (const float*)d_in[0];
    const float* h   = (const float*)d_in[1];
    const int*   ei  = (const int*)  d_in[2];
    const float* ea  = (const float*)d_in[3];
    const float* ew1 = (const float*)d_in[5];
    const float* eb1 = (const float*)d_in[6];
    const float* ew2 = (const float*)d_in[7];
    const float* eb2 = (const float*)d_in[8];
    const float* cw1 = (const float*)d_in[9];
    const float* cb1 = (const float*)d_in[10];
    const float* cw2 = (const float*)d_in[11];
    const float* cb2 = (const float*)d_in[12];
    const float* nw1 = (const float*)d_in[13];
    const float* nb1 = (const float*)d_in[14];
    const float* nw2 = (const float*)d_in[15];
    const float* nb2 = (const float*)d_in[16];

    int N = in_sizes[0] / (3 * T);
    int E = in_sizes[3] / (HE * T);

    float* out_x = (float*)d_out;
    float* out_h = out_x + (size_t)N * 3 * T;

    const int smem_bytes = (KPAD * STRIDE + 2 * KCHUNK * HD) * sizeof(float);
    cudaFuncSetAttribute(edge_kernel, cudaFuncAttributeMaxDynamicSharedMemorySize,
                         smem_bytes);

    zero_kernel<<<2048, 256>>>(N);
    edge_kernel<<<(E + EPB - 1) / EPB, 256, smem_bytes>>>(
        x, h, ei, ea, ew1, eb1, ew2, eb2, cw1, cb1, cw2, cb2, E);
    node_kernel<<<(N + NPB - 1) / NPB, 128>>>(x, h, nw1, nb1, nw2, nb2,
                                              out_x, out_h, N);
}

// round 7
// speedup vs baseline: 3.3980x; 1.4604x over previous
#include <cuda_runtime.h>

#define T    4
#define HH   64
#define HE   16
#define HD   128
#define EPB  32          // edges per edge-block
#define ROWS 128         // EPB*T rows per block
#define STRIDE 132       // padded row length (floats) in A buffer
#define NPRE 32          // nodes per precompute block
#define NKIN 192
#define NPB  4
#define RPB  16
#define MAXN 20000
#define EPSF 1e-8f

typedef unsigned long long u64;

// Scratch (device globals — no allocation allowed; zero-init .bss)
__device__ float g_mi[MAXN * HD * T];    // segment-summed m_ij  [N,HD,T]
__device__ float g_agg[MAXN * 3 * T];    // coord aggregate      [N,3,T]
__device__ float g_cnt[MAXN];            // edge counts          [N]
__device__ float g_p1[(size_t)MAXN * T * HD];  // h[n] @ W1[0:64]   [N,T,HD]
__device__ float g_p2[(size_t)MAXN * T * HD];  // h[n] @ W1[64:128] [N,T,HD]
__device__ float g_zerobias[HD];         // stays zero

__device__ __forceinline__ float silu_f(float v) {
    return v / (1.0f + __expf(-v));
}

// packed fp32x2 FMA: d = a*b + d  (Blackwell FFMA2)
#define FMA2(d, a, b) asm("fma.rn.f32x2 %0, %1, %2, %0;" : "+l"(d) : "l"(a), "l"(b))

__device__ __forceinline__ u64 packab(float a, float b) {
    u64 r; asm("mov.b64 %0, {%1, %2};" : "=l"(r) : "f"(a), "f"(b)); return r;
}
__device__ __forceinline__ u64 pack2(float v) { return packab(v, v); }
__device__ __forceinline__ void unpack2(u64 v, float& lo, float& hi) {
    asm("mov.b64 {%0, %1}, %2;" : "=f"(lo), "=f"(hi) : "l"(v));
}

// ---------------------------------------------------------------------------
// Round-3 register-tiled GEMM phase over a 128-row x 128-col tile.
// Thread (ty 0..15, tx 0..15): rows ty*8..+7; cols {4tx..4tx+3, 64+4tx..+3}.
// out[r][c]: c 0..3 -> col 4tx+c ; c 4..7 -> col 60+4tx+c.
// ---------------------------------------------------------------------------
template<int NCHUNK, int KLIM, bool ACT>
__device__ __forceinline__ void gemm_phase(
    const float* __restrict__ sA, float* __restrict__ sW,
    const float* __restrict__ gW, const float* __restrict__ gB,
    int tid, int tx, int ty, float (&out)[8][8])
{
    u64 acc[8][4];
    {
        float4 bA = *(const float4*)(gB + 4 * tx);
        float4 bB = *(const float4*)(gB + 64 + 4 * tx);
        u64 i0 = packab(bA.x, bA.y), i1 = packab(bA.z, bA.w);
        u64 i2 = packab(bB.x, bB.y), i3 = packab(bB.z, bB.w);
#pragma unroll
        for (int r = 0; r < 8; r++) {
            acc[r][0] = i0; acc[r][1] = i1; acc[r][2] = i2; acc[r][3] = i3;
        }
    }

    float4 pre[4];
#pragma unroll
    for (int i = 0; i < 4; i++) {
        int off = i * 1024 + tid * 4;
        int kg = off >> 7;
        pre[i] = (kg < KLIM) ? *(const float4*)(gW + kg * HD + (off & 127))
                             : make_float4(0.f, 0.f, 0.f, 0.f);
    }

#pragma unroll 1
    for (int kc = 0; kc < NCHUNK; kc++) {
        __syncthreads();                       // prev chunk consumers done
#pragma unroll
        for (int i = 0; i < 4; i++)
            *(float4*)(sW + i * 1024 + tid * 4) = pre[i];
        __syncthreads();
        if (kc + 1 < NCHUNK) {
#pragma unroll
            for (int i = 0; i < 4; i++) {
                int off = i * 1024 + tid * 4;
                int kg = (kc + 1) * 32 + (off >> 7);
                pre[i] = (kg < KLIM) ? *(const float4*)(gW + kg * HD + (off & 127))
                                     : make_float4(0.f, 0.f, 0.f, 0.f);
            }
        }
        const float* ap = sA + (kc * 32) * STRIDE + ty * 8;
#pragma unroll 8
        for (int kk = 0; kk < 32; kk++) {
            float4 a0 = *(const float4*)(ap);
            float4 a1 = *(const float4*)(ap + 4);
            ap += STRIDE;
            ulonglong2 bA = *(const ulonglong2*)(sW + kk * HD + 4 * tx);
            ulonglong2 bB = *(const ulonglong2*)(sW + kk * HD + 64 + 4 * tx);
            float av[8] = {a0.x, a0.y, a0.z, a0.w, a1.x, a1.y, a1.z, a1.w};
#pragma unroll
            for (int r = 0; r < 8; r++) {
                u64 ar = pack2(av[r]);
                FMA2(acc[r][0], ar, bA.x);
                FMA2(acc[r][1], ar, bA.y);
                FMA2(acc[r][2], ar, bB.x);
                FMA2(acc[r][3], ar, bB.y);
            }
        }
    }

#pragma unroll
    for (int r = 0; r < 8; r++)
#pragma unroll
        for (int cp = 0; cp < 4; cp++) {
            float lo, hi; unpack2(acc[r][cp], lo, hi);
            out[r][cp * 2]     = ACT ? silu_f(lo) : lo;
            out[r][cp * 2 + 1] = ACT ? silu_f(hi) : hi;
        }
}

__global__ void zero_kernel(int n) {
    int stride = gridDim.x * blockDim.x;
    int base = blockIdx.x * blockDim.x + threadIdx.x;
    for (int i = base; i < n * HD * T; i += stride) g_mi[i] = 0.0f;
    for (int i = base; i < n * 3 * T;  i += stride) g_agg[i] = 0.0f;
    for (int i = base; i < n;          i += stride) g_cnt[i] = 0.0f;
}

// ---------------------------------------------------------------------------
// Precompute P1 = h @ W1[0:64], P2 = h @ W1[64:128] per node (80k rows).
// Block: 32 consecutive nodes = 128 rows (row = nl*4 + t).
// ---------------------------------------------------------------------------
__global__ __launch_bounds__(256, 2) void pre_kernel(
    const float* __restrict__ h, const float* __restrict__ w1, int N)
{
    extern __shared__ float sm[];
    float* s_h = sm;                           // 64 * STRIDE
    float* s_w = sm + HH * STRIDE;             // 32 * HD

    const int tid = threadIdx.x;
    const int tx  = tid & 15;
    const int ty  = tid >> 4;
    const int n0  = blockIdx.x * NPRE;

    // gather h: 64 ch x 32 nodes, float4 over t (coalesced: nodes consecutive)
#pragma unroll
    for (int it = 0; it < 8; it++) {
        int idx = it * 256 + tid;              // 2048 float4 items
        int k = idx & 63;
        int nl = idx >> 6;
        int node = n0 + nl; if (node >= N) node = N - 1;
        float4 v = *(const float4*)(h + ((size_t)node * HH + k) * T);
        *(float4*)(s_h + k * STRIDE + nl * 4) = v;
    }
    // (gemm_phase's first __syncthreads covers gather->compute ordering)

    float o[8][8];
    gemm_phase<2, HH, false>(s_h, s_w, w1, g_zerobias, tid, tx, ty, o);
#pragma unroll
    for (int r = 0; r < 8; r++) {
        int row = ty * 8 + r;
        int node = n0 + (row >> 2), t = row & 3;
        if (node < N) {
            float* p = g_p1 + ((size_t)node * T + t) * HD;
            *(float4*)(p + 4 * tx)      = make_float4(o[r][0], o[r][1], o[r][2], o[r][3]);
            *(float4*)(p + 64 + 4 * tx) = make_float4(o[r][4], o[r][5], o[r][6], o[r][7]);
        }
    }

    gemm_phase<2, HH, false>(s_h, s_w, w1 + HH * HD, g_zerobias, tid, tx, ty, o);
#pragma unroll
    for (int r = 0; r < 8; r++) {
        int row = ty * 8 + r;
        int node = n0 + (row >> 2), t = row & 3;
        if (node < N) {
            float* p = g_p2 + ((size_t)node * T + t) * HD;
            *(float4*)(p + 4 * tx)      = make_float4(o[r][0], o[r][1], o[r][2], o[r][3]);
            *(float4*)(p + 64 + 4 * tx) = make_float4(o[r][4], o[r][5], o[r][6], o[r][7]);
        }
    }
}

// ---------------------------------------------------------------------------
// Edge kernel: layer1 = P1[row] + P2[col] + b1 + n2*W1[128] + ea@W1[129:145]
// then silu; layer2 + coord layer as round-3 gemm_phase.
// ---------------------------------------------------------------------------
__global__ __launch_bounds__(256, 2) void edge_kernel(
    const float* __restrict__ x,
    const int* __restrict__ ei, const float* __restrict__ ea,
    const float* __restrict__ w1, const float* __restrict__ b1,
    const float* __restrict__ w2, const float* __restrict__ b2,
    const float* __restrict__ cw1, const float* __restrict__ cb1,
    const float* __restrict__ cw2, const float* __restrict__ cb2,
    int E)
{
    extern __shared__ float sm[];
    float* s_buf = sm;                         // 128 * STRIDE (mid / m_ij)
    float* s_ea  = sm + HD * STRIDE;           // 16 * STRIDE
    float* s_w   = s_ea + HE * STRIDE;         // 32 * HD
    float* s_part = s_buf;                     // 16*ROWS, overlays s_buf late

    __shared__ int   s_rown[EPB], s_coln[EPB];
    __shared__ float s_xij[EPB][3][T];
    __shared__ float s_n2[ROWS];

    const int tid = threadIdx.x;
    const int tx  = tid & 15;
    const int ty  = tid >> 4;
    const int e0  = blockIdx.x * EPB;

    if (tid < EPB) {
        int eg = e0 + tid;
        if (eg >= E) eg = E - 1;
        s_rown[tid] = ei[eg];
        s_coln[tid] = ei[E + eg];
    }

    // ---- stage W1 rows 129..144 (ea part) + row 128 (n2 weights) into s_w ----
    for (int i = tid; i < 17 * 32; i += 256) {
        int k = i >> 5, cg = i & 31;
        int srcrow = (k == 16) ? 128 : (129 + k);
        *(float4*)(s_w + k * HD + cg * 4) = *(const float4*)(w1 + srcrow * HD + cg * 4);
    }
    __syncthreads();                           // s_rown/s_coln ready too

    // ---- edge_attr gather: 16 ch x 32 edges, float4 over t ----
#pragma unroll
    for (int it = 0; it < 2; it++) {
        int idx = it * 256 + tid;              // 512 items
        int k = idx & 15;
        int e = idx >> 4;
        int eg = e0 + e; if (eg >= E) eg = E - 1;
        float4 v = *(const float4*)(ea + ((size_t)eg * HE + k) * T);
        *(float4*)(s_ea + k * STRIDE + e * 4) = v;
    }
    // ---- x_ij, n2 ----
    if (tid < ROWS) {
        int e = tid >> 2, t = tid & 3;
        int rn = s_rown[e], cn = s_coln[e];
        float n2 = 0.f;
#pragma unroll
        for (int d = 0; d < 3; d++) {
            float v = x[((size_t)rn * 3 + d) * T + t] - x[((size_t)cn * 3 + d) * T + t];
            s_xij[e][d][t] = v;
            n2 += v * v;
        }
        s_n2[tid] = n2;
    }
    __syncthreads();

    // ---- layer 1 ----
    float o1[8][8];
    {
        u64 acc[8][4];
        float4 bA = *(const float4*)(b1 + 4 * tx);
        float4 bB = *(const float4*)(b1 + 64 + 4 * tx);
        float4 wA = *(const float4*)(s_w + 16 * HD + 4 * tx);
        float4 wB = *(const float4*)(s_w + 16 * HD + 64 + 4 * tx);
#pragma unroll
        for (int r = 0; r < 8; r++) {
            int row = ty * 8 + r;
            int e = row >> 2, t = row & 3;
            const float* p1 = g_p1 + ((size_t)s_rown[e] * T + t) * HD;
            const float* p2 = g_p2 + ((size_t)s_coln[e] * T + t) * HD;
            float4 a1 = *(const float4*)(p1 + 4 * tx);
            float4 c1 = *(const float4*)(p1 + 64 + 4 * tx);
            float4 a2 = *(const float4*)(p2 + 4 * tx);
            float4 c2 = *(const float4*)(p2 + 64 + 4 * tx);
            float n2r = s_n2[row];
            float v0 = bA.x + a1.x + a2.x + n2r * wA.x;
            float v1 = bA.y + a1.y + a2.y + n2r * wA.y;
            float v2 = bA.z + a1.z + a2.z + n2r * wA.z;
            float v3 = bA.w + a1.w + a2.w + n2r * wA.w;
            float v4 = bB.x + c1.x + c2.x + n2r * wB.x;
            float v5 = bB.y + c1.y + c2.y + n2r * wB.y;
            float v6 = bB.z + c1.z + c2.z + n2r * wB.z;
            float v7 = bB.w + c1.w + c2.w + n2r * wB.w;
            acc[r][0] = packab(v0, v1); acc[r][1] = packab(v2, v3);
            acc[r][2] = packab(v4, v5); acc[r][3] = packab(v6, v7);
        }
        const float* ap = s_ea + ty * 8;
#pragma unroll
        for (int k = 0; k < HE; k++) {
            float4 a0 = *(const float4*)(ap);
            float4 a1 = *(const float4*)(ap + 4);
            ap += STRIDE;
            ulonglong2 wp0 = *(const ulonglong2*)(s_w + k * HD + 4 * tx);
            ulonglong2 wp1 = *(const ulonglong2*)(s_w + k * HD + 64 + 4 * tx);
            float av[8] = {a0.x, a0.y, a0.z, a0.w, a1.x, a1.y, a1.z, a1.w};
#pragma unroll
            for (int r = 0; r < 8; r++) {
                u64 ar = pack2(av[r]);
                FMA2(acc[r][0], ar, wp0.x);
                FMA2(acc[r][1], ar, wp0.y);
                FMA2(acc[r][2], ar, wp1.x);
                FMA2(acc[r][3], ar, wp1.y);
            }
        }
#pragma unroll
        for (int r = 0; r < 8; r++)
#pragma unroll
            for (int cp = 0; cp < 4; cp++) {
                float lo, hi; unpack2(acc[r][cp], lo, hi);
                o1[r][2 * cp]     = silu_f(lo);
                o1[r][2 * cp + 1] = silu_f(hi);
            }
    }
    __syncthreads();                           // s_w readers done (before restage)

    // ---- mid -> s_buf ----
#pragma unroll
    for (int c = 0; c < 8; c++) {
        int col = (c < 4) ? 4 * tx + c : 60 + 4 * tx + c;
        *(float4*)(s_buf + col * STRIDE + ty * 8) =
            make_float4(o1[0][c], o1[1][c], o1[2][c], o1[3][c]);
        *(float4*)(s_buf + col * STRIDE + ty * 8 + 4) =
            make_float4(o1[4][c], o1[5][c], o1[6][c], o1[7][c]);
    }

    // ---- layer 2: m_ij = silu(mid @ W2 + b2) ----
    float o2[8][8];
    gemm_phase<4, HD, true>(s_buf, s_w, w2, b2, tid, tx, ty, o2);

    // ---- scatter m_i ----
#pragma unroll
    for (int eh = 0; eh < 2; eh++) {
        int el = 2 * ty + eh;
        if (e0 + el < E) {
            int node = s_rown[el];
#pragma unroll
            for (int c = 0; c < 8; c++) {
                int col = (c < 4) ? 4 * tx + c : 60 + 4 * tx + c;
                float* p = &g_mi[((size_t)node * HD + col) * T];
                asm volatile("red.global.add.v4.f32 [%0], {%1,%2,%3,%4};"
                             :: "l"(p), "f"(o2[eh * 4 + 0][c]), "f"(o2[eh * 4 + 1][c]),
                                "f"(o2[eh * 4 + 2][c]), "f"(o2[eh * 4 + 3][c])
                             : "memory");
            }
        }
    }

    // ---- m_ij -> smem for coord MLP ----
    __syncthreads();
#pragma unroll
    for (int c = 0; c < 8; c++) {
        int col = (c < 4) ? 4 * tx + c : 60 + 4 * tx + c;
        *(float4*)(s_buf + col * STRIDE + ty * 8) =
            make_float4(o2[0][c], o2[1][c], o2[2][c], o2[3][c]);
        *(float4*)(s_buf + col * STRIDE + ty * 8 + 4) =
            make_float4(o2[4][c], o2[5][c], o2[6][c], o2[7][c]);
    }

    // ---- coord layer 1: silu(m_ij @ cw1 + cb1) ----
    float o3[8][8];
    gemm_phase<4, HD, true>(s_buf, s_w, cw1, cb1, tid, tx, ty, o3);

    // ---- coord projection to 1: partials ----
    {
        float4 c2a = *(const float4*)(cw2 + 4 * tx);
        float4 c2b = *(const float4*)(cw2 + 64 + 4 * tx);
        float cw[8] = {c2a.x, c2a.y, c2a.z, c2a.w, c2b.x, c2b.y, c2b.z, c2b.w};
        float p[8];
#pragma unroll
        for (int r = 0; r < 8; r++) {
            float s = 0.f;
#pragma unroll
            for (int c = 0; c < 8; c++) s += o3[r][c] * cw[c];
            p[r] = s;
        }
        __syncthreads();                       // s_buf reads (GEMM3) done
        *(float4*)(s_part + tx * ROWS + ty * 8) = make_float4(p[0], p[1], p[2], p[3]);
        *(float4*)(s_part + tx * ROWS + ty * 8 + 4) = make_float4(p[4], p[5], p[6], p[7]);
    }
    __syncthreads();

    if (tid < ROWS) {
        float cval = cb2[0];
#pragma unroll
        for (int q = 0; q < 16; q++) cval += s_part[q * ROWS + tid];
        cval /= (sqrtf(s_n2[tid] + EPSF) + 1.0f);
        int e = tid >> 2, t = tid & 3;
        if (e0 + e < E) {
            int node = s_rown[e];
#pragma unroll
            for (int d = 0; d < 3; d++)
                atomicAdd(&g_agg[((size_t)node * 3 + d) * T + t], cval * s_xij[e][d][t]);
            if (t == 0) atomicAdd(&g_cnt[node], 1.0f);
        }
    }
}

// ---------------------------------------------------------------------------
// Node kernel (unchanged from round 3)
// ---------------------------------------------------------------------------
__global__ __launch_bounds__(128) void node_kernel(
    const float* __restrict__ x, const float* __restrict__ h,
    const float* __restrict__ nw1, const float* __restrict__ nb1,
    const float* __restrict__ nw2, const float* __restrict__ nb2,
    float* __restrict__ out_x, float* __restrict__ out_h, int N)
{
    __shared__ __align__(16) float s_in[NKIN][RPB];
    __shared__ __align__(16) float s_a[HD][RPB];

    const int tid = threadIdx.x;
    const int n0  = blockIdx.x * NPB;

    if (tid < NPB * 12) {
        int n = n0 + tid / 12;
        if (n < N) {
            int rem = tid % 12, d = rem >> 2, t = rem & 3;
            float cv = fmaxf(g_cnt[n], 1.0f);
            int off = (n * 3 + d) * T + t;
            out_x[off] = x[off] + g_agg[off] / cv;
        }
    }

#pragma unroll
    for (int it = 0; it < 24; it++) {
        int idx = it * 128 + tid;
        int k = idx >> 4, i = idx & 15;
        int n = n0 + (i >> 2), t = i & 3;
        int nn = (n < N) ? n : 0;
        float v = (k < HH) ? h[(nn * HH + k) * T + t]
                           : g_mi[(nn * HD + (k - HH)) * T + t];
        s_in[k][i] = v;
    }
    __syncthreads();

    // layer 1: 192 -> 128, silu
    {
        u64 acc[8];
        u64 bp = pack2(nb1[tid]);
#pragma unroll
        for (int i = 0; i < 8; i++) acc[i] = bp;
#pragma unroll 4
        for (int k = 0; k < NKIN; k++) {
            u64 wp = pack2(nw1[k * HD + tid]);
            const ulonglong2* pp = reinterpret_cast<const ulonglong2*>(s_in[k]);
            ulonglong2 p0 = pp[0], p1 = pp[1];
            FMA2(acc[0], p0.x, wp); FMA2(acc[1], p0.y, wp);
            FMA2(acc[2], p1.x, wp); FMA2(acc[3], p1.y, wp);
            ulonglong2 p2 = pp[2], p3 = pp[3];
            FMA2(acc[4], p2.x, wp); FMA2(acc[5], p2.y, wp);
            FMA2(acc[6], p3.x, wp); FMA2(acc[7], p3.y, wp);
        }
#pragma unroll
        for (int i = 0; i < 8; i++) {
            float lo, hi; unpack2(acc[i], lo, hi);
            s_a[tid][2 * i]     = silu_f(lo);
            s_a[tid][2 * i + 1] = silu_f(hi);
        }
    }
    __syncthreads();

    // layer 2: 128 -> 64, linear
    if (tid < HH) {
        u64 acc[8];
        u64 bp = pack2(nb2[tid]);
#pragma unroll
        for (int i = 0; i < 8; i++) acc[i] = bp;
#pragma unroll 4
        for (int k = 0; k < HD; k++) {
            u64 wp = pack2(nw2[k * HH + tid]);
            const ulonglong2* pp = reinterpret_cast<const ulonglong2*>(s_a[k]);
            ulonglong2 p0 = pp[0], p1 = pp[1];
            FMA2(acc[0], p0.x, wp); FMA2(acc[1], p0.y, wp);
            FMA2(acc[2], p1.x, wp); FMA2(acc[3], p1.y, wp);
            ulonglong2 p2 = pp[2], p3 = pp[3];
            FMA2(acc[4], p2.x, wp); FMA2(acc[5], p2.y, wp);
            FMA2(acc[6], p3.x, wp); FMA2(acc[7], p3.y, wp);
        }
#pragma unroll
        for (int nl = 0; nl < NPB; nl++) {
            int n = n0 + nl;
            if (n < N) {
                float4 o;
                unpack2(acc[2 * nl],     o.x, o.y);
                unpack2(acc[2 * nl + 1], o.z, o.w);
                *reinterpret_cast<float4*>(&out_h[(n * HH + tid) * T]) = o;
            }
        }
    }
}

extern "C" void kernel_launch(void* const* d_in, const int* in_sizes, int n_in,
                              void* d_out, int out_size)
{
    const float* x   = (const float*)d_in[0];
    const float* h   = (const float*)d_in[1];
    const int*   ei  = (const int*)  d_in[2];
    const float* ea  = (const float*)d_in[3];
    const float* ew1 = (const float*)d_in[5];
    const float* eb1 = (const float*)d_in[6];
    const float* ew2 = (const float*)d_in[7];
    const float* eb2 = (const float*)d_in[8];
    const float* cw1 = (const float*)d_in[9];
    const float* cb1 = (const float*)d_in[10];
    const float* cw2 = (const float*)d_in[11];
    const float* cb2 = (const float*)d_in[12];
    const float* nw1 = (const float*)d_in[13];
    const float* nb1 = (const float*)d_in[14];
    const float* nw2 = (const float*)d_in[15];
    const float* nb2 = (const float*)d_in[16];

    int N = in_sizes[0] / (3 * T);
    int E = in_sizes[3] / (HE * T);

    float* out_x = (float*)d_out;
    float* out_h = out_x + (size_t)N * 3 * T;

    const int pre_smem  = (HH * STRIDE + 32 * HD) * sizeof(float);
    const int edge_smem = ((HD + HE) * STRIDE + 32 * HD) * sizeof(float);
    cudaFuncSetAttribute(pre_kernel, cudaFuncAttributeMaxDynamicSharedMemorySize,
                         pre_smem);
    cudaFuncSetAttribute(edge_kernel, cudaFuncAttributeMaxDynamicSharedMemorySize,
                         edge_smem);

    zero_kernel<<<2048, 256>>>(N);
    pre_kernel<<<(N + NPRE - 1) / NPRE, 256, pre_smem>>>(h, ew1, N);
    edge_kernel<<<(E + EPB - 1) / EPB, 256, edge_smem>>>(
        x, ei, ea, ew1, eb1, ew2, eb2, cw1, cb1, cw2, cb2, E);
    node_kernel<<<(N + NPB - 1) / NPB, 128>>>(x, h, nw1, nb1, nw2, nb2,
                                              out_x, out_h, N);
}

// round 8
// speedup vs baseline: 3.4698x; 1.0211x over previous
#include <cuda_runtime.h>

#define T    4
#define HH   64
#define HE   16
#define HD   128
#define EPB  32          // edges per edge-block
#define ROWS 128         // EPB*T rows per block
#define STRIDE 132       // padded row length (floats) in A buffer
#define NPRE 32          // nodes per precompute block
#define NPB  32          // nodes per node-block (128 rows)
#define MAXN 20000
#define EPSF 1e-8f

typedef unsigned long long u64;

// Scratch (device globals — no allocation allowed; zero-init .bss)
__device__ float g_mi[MAXN * HD * T];    // segment-summed m_ij  [N,HD,T]
__device__ float g_agg[MAXN * 3 * T];    // coord aggregate      [N,3,T]
__device__ float g_cnt[MAXN];            // edge counts          [N]
__device__ float g_p1[(size_t)MAXN * T * HD];  // h[n] @ W1[0:64]   [N,T,HD]
__device__ float g_p2[(size_t)MAXN * T * HD];  // h[n] @ W1[64:128] [N,T,HD]
__device__ float g_zerobias[HD];         // stays zero

__device__ __forceinline__ float silu_f(float v) {
    return v / (1.0f + __expf(-v));
}

// packed fp32x2 FMA: d = a*b + d  (Blackwell FFMA2)
#define FMA2(d, a, b) asm("fma.rn.f32x2 %0, %1, %2, %0;" : "+l"(d) : "l"(a), "l"(b))

__device__ __forceinline__ u64 packab(float a, float b) {
    u64 r; asm("mov.b64 %0, {%1, %2};" : "=l"(r) : "f"(a), "f"(b)); return r;
}
__device__ __forceinline__ u64 pack2(float v) { return packab(v, v); }
__device__ __forceinline__ void unpack2(u64 v, float& lo, float& hi) {
    asm("mov.b64 {%0, %1}, %2;" : "=f"(lo), "=f"(hi) : "l"(v));
}

// ---------------------------------------------------------------------------
// Round-3 register-tiled GEMM phase over a 128-row x 128-col tile.
// Thread (ty 0..15, tx 0..15): rows ty*8..+7; cols {4tx..4tx+3, 64+4tx..+3}.
// out[r][c]: c 0..3 -> col 4tx+c ; c 4..7 -> col 60+4tx+c.
// ---------------------------------------------------------------------------
template<int NCHUNK, int KLIM, bool ACT>
__device__ __forceinline__ void gemm_phase(
    const float* __restrict__ sA, float* __restrict__ sW,
    const float* __restrict__ gW, const float* __restrict__ gB,
    int tid, int tx, int ty, float (&out)[8][8])
{
    u64 acc[8][4];
    {
        float4 bA = *(const float4*)(gB + 4 * tx);
        float4 bB = *(const float4*)(gB + 64 + 4 * tx);
        u64 i0 = packab(bA.x, bA.y), i1 = packab(bA.z, bA.w);
        u64 i2 = packab(bB.x, bB.y), i3 = packab(bB.z, bB.w);
#pragma unroll
        for (int r = 0; r < 8; r++) {
            acc[r][0] = i0; acc[r][1] = i1; acc[r][2] = i2; acc[r][3] = i3;
        }
    }

    float4 pre[4];
#pragma unroll
    for (int i = 0; i < 4; i++) {
        int off = i * 1024 + tid * 4;
        int kg = off >> 7;
        pre[i] = (kg < KLIM) ? *(const float4*)(gW + kg * HD + (off & 127))
                             : make_float4(0.f, 0.f, 0.f, 0.f);
    }

#pragma unroll 1
    for (int kc = 0; kc < NCHUNK; kc++) {
        __syncthreads();                       // prev chunk consumers done
#pragma unroll
        for (int i = 0; i < 4; i++)
            *(float4*)(sW + i * 1024 + tid * 4) = pre[i];
        __syncthreads();
        if (kc + 1 < NCHUNK) {
#pragma unroll
            for (int i = 0; i < 4; i++) {
                int off = i * 1024 + tid * 4;
                int kg = (kc + 1) * 32 + (off >> 7);
                pre[i] = (kg < KLIM) ? *(const float4*)(gW + kg * HD + (off & 127))
                                     : make_float4(0.f, 0.f, 0.f, 0.f);
            }
        }
        const float* ap = sA + (kc * 32) * STRIDE + ty * 8;
#pragma unroll 8
        for (int kk = 0; kk < 32; kk++) {
            float4 a0 = *(const float4*)(ap);
            float4 a1 = *(const float4*)(ap + 4);
            ap += STRIDE;
            ulonglong2 bA = *(const ulonglong2*)(sW + kk * HD + 4 * tx);
            ulonglong2 bB = *(const ulonglong2*)(sW + kk * HD + 64 + 4 * tx);
            float av[8] = {a0.x, a0.y, a0.z, a0.w, a1.x, a1.y, a1.z, a1.w};
#pragma unroll
            for (int r = 0; r < 8; r++) {
                u64 ar = pack2(av[r]);
                FMA2(acc[r][0], ar, bA.x);
                FMA2(acc[r][1], ar, bA.y);
                FMA2(acc[r][2], ar, bB.x);
                FMA2(acc[r][3], ar, bB.y);
            }
        }
    }

#pragma unroll
    for (int r = 0; r < 8; r++)
#pragma unroll
        for (int cp = 0; cp < 4; cp++) {
            float lo, hi; unpack2(acc[r][cp], lo, hi);
            out[r][cp * 2]     = ACT ? silu_f(lo) : lo;
            out[r][cp * 2 + 1] = ACT ? silu_f(hi) : hi;
        }
}

__global__ void zero_kernel(int n) {
    int stride = gridDim.x * blockDim.x;
    int base = blockIdx.x * blockDim.x + threadIdx.x;
    for (int i = base; i < n * HD * T; i += stride) g_mi[i] = 0.0f;
    for (int i = base; i < n * 3 * T;  i += stride) g_agg[i] = 0.0f;
    for (int i = base; i < n;          i += stride) g_cnt[i] = 0.0f;
}

// ---------------------------------------------------------------------------
// Precompute P1 = h @ W1[0:64], P2 = h @ W1[64:128] per node (80k rows).
// ---------------------------------------------------------------------------
__global__ __launch_bounds__(256, 2) void pre_kernel(
    const float* __restrict__ h, const float* __restrict__ w1, int N)
{
    extern __shared__ float sm[];
    float* s_h = sm;                           // 64 * STRIDE
    float* s_w = sm + HH * STRIDE;             // 32 * HD

    const int tid = threadIdx.x;
    const int tx  = tid & 15;
    const int ty  = tid >> 4;
    const int n0  = blockIdx.x * NPRE;

#pragma unroll
    for (int it = 0; it < 8; it++) {
        int idx = it * 256 + tid;              // 2048 float4 items
        int k = idx & 63;
        int nl = idx >> 6;
        int node = n0 + nl; if (node >= N) node = N - 1;
        float4 v = *(const float4*)(h + ((size_t)node * HH + k) * T);
        *(float4*)(s_h + k * STRIDE + nl * 4) = v;
    }
    // (gemm_phase's first __syncthreads covers gather->compute ordering)

    float o[8][8];
    gemm_phase<2, HH, false>(s_h, s_w, w1, g_zerobias, tid, tx, ty, o);
#pragma unroll
    for (int r = 0; r < 8; r++) {
        int row = ty * 8 + r;
        int node = n0 + (row >> 2), t = row & 3;
        if (node < N) {
            float* p = g_p1 + ((size_t)node * T + t) * HD;
            *(float4*)(p + 4 * tx)      = make_float4(o[r][0], o[r][1], o[r][2], o[r][3]);
            *(float4*)(p + 64 + 4 * tx) = make_float4(o[r][4], o[r][5], o[r][6], o[r][7]);
        }
    }

    gemm_phase<2, HH, false>(s_h, s_w, w1 + HH * HD, g_zerobias, tid, tx, ty, o);
#pragma unroll
    for (int r = 0; r < 8; r++) {
        int row = ty * 8 + r;
        int node = n0 + (row >> 2), t = row & 3;
        if (node < N) {
            float* p = g_p2 + ((size_t)node * T + t) * HD;
            *(float4*)(p + 4 * tx)      = make_float4(o[r][0], o[r][1], o[r][2], o[r][3]);
            *(float4*)(p + 64 + 4 * tx) = make_float4(o[r][4], o[r][5], o[r][6], o[r][7]);
        }
    }
}

// ---------------------------------------------------------------------------
// Edge kernel (unchanged from round 7)
// ---------------------------------------------------------------------------
__global__ __launch_bounds__(256, 2) void edge_kernel(
    const float* __restrict__ x,
    const int* __restrict__ ei, const float* __restrict__ ea,
    const float* __restrict__ w1, const float* __restrict__ b1,
    const float* __restrict__ w2, const float* __restrict__ b2,
    const float* __restrict__ cw1, const float* __restrict__ cb1,
    const float* __restrict__ cw2, const float* __restrict__ cb2,
    int E)
{
    extern __shared__ float sm[];
    float* s_buf = sm;                         // 128 * STRIDE (mid / m_ij)
    float* s_ea  = sm + HD * STRIDE;           // 16 * STRIDE
    float* s_w   = s_ea + HE * STRIDE;         // 32 * HD
    float* s_part = s_buf;                     // 16*ROWS, overlays s_buf late

    __shared__ int   s_rown[EPB], s_coln[EPB];
    __shared__ float s_xij[EPB][3][T];
    __shared__ float s_n2[ROWS];

    const int tid = threadIdx.x;
    const int tx  = tid & 15;
    const int ty  = tid >> 4;
    const int e0  = blockIdx.x * EPB;

    if (tid < EPB) {
        int eg = e0 + tid;
        if (eg >= E) eg = E - 1;
        s_rown[tid] = ei[eg];
        s_coln[tid] = ei[E + eg];
    }

    // ---- stage W1 rows 129..144 (ea part) + row 128 (n2 weights) into s_w ----
    for (int i = tid; i < 17 * 32; i += 256) {
        int k = i >> 5, cg = i & 31;
        int srcrow = (k == 16) ? 128 : (129 + k);
        *(float4*)(s_w + k * HD + cg * 4) = *(const float4*)(w1 + srcrow * HD + cg * 4);
    }
    __syncthreads();                           // s_rown/s_coln ready too

    // ---- edge_attr gather: 16 ch x 32 edges, float4 over t ----
#pragma unroll
    for (int it = 0; it < 2; it++) {
        int idx = it * 256 + tid;              // 512 items
        int k = idx & 15;
        int e = idx >> 4;
        int eg = e0 + e; if (eg >= E) eg = E - 1;
        float4 v = *(const float4*)(ea + ((size_t)eg * HE + k) * T);
        *(float4*)(s_ea + k * STRIDE + e * 4) = v;
    }
    // ---- x_ij, n2 ----
    if (tid < ROWS) {
        int e = tid >> 2, t = tid & 3;
        int rn = s_rown[e], cn = s_coln[e];
        float n2 = 0.f;
#pragma unroll
        for (int d = 0; d < 3; d++) {
            float v = x[((size_t)rn * 3 + d) * T + t] - x[((size_t)cn * 3 + d) * T + t];
            s_xij[e][d][t] = v;
            n2 += v * v;
        }
        s_n2[tid] = n2;
    }
    __syncthreads();

    // ---- layer 1 ----
    float o1[8][8];
    {
        u64 acc[8][4];
        float4 bA = *(const float4*)(b1 + 4 * tx);
        float4 bB = *(const float4*)(b1 + 64 + 4 * tx);
        float4 wA = *(const float4*)(s_w + 16 * HD + 4 * tx);
        float4 wB = *(const float4*)(s_w + 16 * HD + 64 + 4 * tx);
#pragma unroll
        for (int r = 0; r < 8; r++) {
            int row = ty * 8 + r;
            int e = row >> 2, t = row & 3;
            const float* p1 = g_p1 + ((size_t)s_rown[e] * T + t) * HD;
            const float* p2 = g_p2 + ((size_t)s_coln[e] * T + t) * HD;
            float4 a1 = *(const float4*)(p1 + 4 * tx);
            float4 c1 = *(const float4*)(p1 + 64 + 4 * tx);
            float4 a2 = *(const float4*)(p2 + 4 * tx);
            float4 c2 = *(const float4*)(p2 + 64 + 4 * tx);
            float n2r = s_n2[row];
            float v0 = bA.x + a1.x + a2.x + n2r * wA.x;
            float v1 = bA.y + a1.y + a2.y + n2r * wA.y;
            float v2 = bA.z + a1.z + a2.z + n2r * wA.z;
            float v3 = bA.w + a1.w + a2.w + n2r * wA.w;
            float v4 = bB.x + c1.x + c2.x + n2r * wB.x;
            float v5 = bB.y + c1.y + c2.y + n2r * wB.y;
            float v6 = bB.z + c1.z + c2.z + n2r * wB.z;
            float v7 = bB.w + c1.w + c2.w + n2r * wB.w;
            acc[r][0] = packab(v0, v1); acc[r][1] = packab(v2, v3);
            acc[r][2] = packab(v4, v5); acc[r][3] = packab(v6, v7);
        }
        const float* ap = s_ea + ty * 8;
#pragma unroll
        for (int k = 0; k < HE; k++) {
            float4 a0 = *(const float4*)(ap);
            float4 a1 = *(const float4*)(ap + 4);
            ap += STRIDE;
            ulonglong2 wp0 = *(const ulonglong2*)(s_w + k * HD + 4 * tx);
            ulonglong2 wp1 = *(const ulonglong2*)(s_w + k * HD + 64 + 4 * tx);
            float av[8] = {a0.x, a0.y, a0.z, a0.w, a1.x, a1.y, a1.z, a1.w};
#pragma unroll
            for (int r = 0; r < 8; r++) {
                u64 ar = pack2(av[r]);
                FMA2(acc[r][0], ar, wp0.x);
                FMA2(acc[r][1], ar, wp0.y);
                FMA2(acc[r][2], ar, wp1.x);
                FMA2(acc[r][3], ar, wp1.y);
            }
        }
#pragma unroll
        for (int r = 0; r < 8; r++)
#pragma unroll
            for (int cp = 0; cp < 4; cp++) {
                float lo, hi; unpack2(acc[r][cp], lo, hi);
                o1[r][2 * cp]     = silu_f(lo);
                o1[r][2 * cp + 1] = silu_f(hi);
            }
    }
    __syncthreads();                           // s_w readers done (before restage)

    // ---- mid -> s_buf ----
#pragma unroll
    for (int c = 0; c < 8; c++) {
        int col = (c < 4) ? 4 * tx + c : 60 + 4 * tx + c;
        *(float4*)(s_buf + col * STRIDE + ty * 8) =
            make_float4(o1[0][c], o1[1][c], o1[2][c], o1[3][c]);
        *(float4*)(s_buf + col * STRIDE + ty * 8 + 4) =
            make_float4(o1[4][c], o1[5][c], o1[6][c], o1[7][c]);
    }

    // ---- layer 2: m_ij = silu(mid @ W2 + b2) ----
    float o2[8][8];
    gemm_phase<4, HD, true>(s_buf, s_w, w2, b2, tid, tx, ty, o2);

    // ---- scatter m_i ----
#pragma unroll
    for (int eh = 0; eh < 2; eh++) {
        int el = 2 * ty + eh;
        if (e0 + el < E) {
            int node = s_rown[el];
#pragma unroll
            for (int c = 0; c < 8; c++) {
                int col = (c < 4) ? 4 * tx + c : 60 + 4 * tx + c;
                float* p = &g_mi[((size_t)node * HD + col) * T];
                asm volatile("red.global.add.v4.f32 [%0], {%1,%2,%3,%4};"
                             :: "l"(p), "f"(o2[eh * 4 + 0][c]), "f"(o2[eh * 4 + 1][c]),
                                "f"(o2[eh * 4 + 2][c]), "f"(o2[eh * 4 + 3][c])
                             : "memory");
            }
        }
    }

    // ---- m_ij -> smem for coord MLP ----
    __syncthreads();
#pragma unroll
    for (int c = 0; c < 8; c++) {
        int col = (c < 4) ? 4 * tx + c : 60 + 4 * tx + c;
        *(float4*)(s_buf + col * STRIDE + ty * 8) =
            make_float4(o2[0][c], o2[1][c], o2[2][c], o2[3][c]);
        *(float4*)(s_buf + col * STRIDE + ty * 8 + 4) =
            make_float4(o2[4][c], o2[5][c], o2[6][c], o2[7][c]);
    }

    // ---- coord layer 1: silu(m_ij @ cw1 + cb1) ----
    float o3[8][8];
    gemm_phase<4, HD, true>(s_buf, s_w, cw1, cb1, tid, tx, ty, o3);

    // ---- coord projection to 1: partials ----
    {
        float4 c2a = *(const float4*)(cw2 + 4 * tx);
        float4 c2b = *(const float4*)(cw2 + 64 + 4 * tx);
        float cw[8] = {c2a.x, c2a.y, c2a.z, c2a.w, c2b.x, c2b.y, c2b.z, c2b.w};
        float p[8];
#pragma unroll
        for (int r = 0; r < 8; r++) {
            float s = 0.f;
#pragma unroll
            for (int c = 0; c < 8; c++) s += o3[r][c] * cw[c];
            p[r] = s;
        }
        __syncthreads();                       // s_buf reads (GEMM3) done
        *(float4*)(s_part + tx * ROWS + ty * 8) = make_float4(p[0], p[1], p[2], p[3]);
        *(float4*)(s_part + tx * ROWS + ty * 8 + 4) = make_float4(p[4], p[5], p[6], p[7]);
    }
    __syncthreads();

    if (tid < ROWS) {
        float cval = cb2[0];
#pragma unroll
        for (int q = 0; q < 16; q++) cval += s_part[q * ROWS + tid];
        cval /= (sqrtf(s_n2[tid] + EPSF) + 1.0f);
        int e = tid >> 2, t = tid & 3;
        if (e0 + e < E) {
            int node = s_rown[e];
#pragma unroll
            for (int d = 0; d < 3; d++)
                atomicAdd(&g_agg[((size_t)node * 3 + d) * T + t], cval * s_xij[e][d][t]);
            if (t == 0) atomicAdd(&g_cnt[node], 1.0f);
        }
    }
}

// ---------------------------------------------------------------------------
// Node kernel — register-tiled rewrite. 32 nodes = 128 rows per block,
// 256 threads, 8x8 tiles. Layer 1 (192k) accumulates across two A-stages
// in a 128-ch buffer; layer 2 is a 64-col half-width variant.
// ---------------------------------------------------------------------------
__global__ __launch_bounds__(256, 2) void node_kernel(
    const float* __restrict__ x, const float* __restrict__ h,
    const float* __restrict__ nw1, const float* __restrict__ nb1,
    const float* __restrict__ nw2, const float* __restrict__ nb2,
    float* __restrict__ out_x, float* __restrict__ out_h, int N)
{
    extern __shared__ float sm[];
    float* s_buf = sm;                         // 128 ch * STRIDE
    float* s_w   = sm + HD * STRIDE;           // 32 * HD

    const int tid = threadIdx.x;
    const int tx  = tid & 15;
    const int ty  = tid >> 4;
    const int n0  = blockIdx.x * NPB;

    // ---- x_new epilogue: 32 nodes * 12 = 384 items ----
#pragma unroll
    for (int it = 0; it < 2; it++) {
        int idx = it * 256 + tid;
        if (idx < NPB * 12) {
            int n = n0 + idx / 12;
            if (n < N) {
                int rem = idx % 12, d = rem >> 2, t = rem & 3;
                float cv = fmaxf(g_cnt[n], 1.0f);
                int off = (n * 3 + d) * T + t;
                out_x[off] = x[off] + g_agg[off] / cv;
            }
        }
    }

    // ---- stage A part 1: ch 0..127 = [h(64) | m_i ch 0..63] ----
#pragma unroll
    for (int it = 0; it < 16; it++) {
        int idx = it * 256 + tid;              // 4096 float4 items
        int k = idx & 127;
        int nl = idx >> 7;
        int node = n0 + nl; if (node >= N) node = N - 1;
        float4 v = (k < HH)
            ? *(const float4*)(h    + ((size_t)node * HH + k) * T)
            : *(const float4*)(g_mi + ((size_t)node * HD + (k - HH)) * T);
        *(float4*)(s_buf + k * STRIDE + nl * 4) = v;
    }

    // ---- layer 1: acc over k 0..191 in two A-stages ----
    u64 acc[8][4];
    {
        float4 bA = *(const float4*)(nb1 + 4 * tx);
        float4 bB = *(const float4*)(nb1 + 64 + 4 * tx);
        u64 i0 = packab(bA.x, bA.y), i1 = packab(bA.z, bA.w);
        u64 i2 = packab(bB.x, bB.y), i3 = packab(bB.z, bB.w);
#pragma unroll
        for (int r = 0; r < 8; r++) {
            acc[r][0] = i0; acc[r][1] = i1; acc[r][2] = i2; acc[r][3] = i3;
        }
    }

    float4 pre[4];
#pragma unroll
    for (int i = 0; i < 4; i++) {
        int off = i * 1024 + tid * 4;
        pre[i] = *(const float4*)(nw1 + (off >> 7) * HD + (off & 127));
    }

    // part A: 4 chunks over nw1 rows 0..127
#pragma unroll 1
    for (int kc = 0; kc < 4; kc++) {
        __syncthreads();
#pragma unroll
        for (int i = 0; i < 4; i++)
            *(float4*)(s_w + i * 1024 + tid * 4) = pre[i];
        __syncthreads();
        {
            int kbase = (kc + 1) * 32;          // rows 32..191 (valid: 192 total)
            if (kbase < 192) {
#pragma unroll
                for (int i = 0; i < 4; i++) {
                    int off = i * 1024 + tid * 4;
                    pre[i] = *(const float4*)(nw1 + (kbase + (off >> 7)) * HD + (off & 127));
                }
            }
        }
        const float* ap = s_buf + (kc * 32) * STRIDE + ty * 8;
#pragma unroll 8
        for (int kk = 0; kk < 32; kk++) {
            float4 a0 = *(const float4*)(ap);
            float4 a1 = *(const float4*)(ap + 4);
            ap += STRIDE;
            ulonglong2 bA = *(const ulonglong2*)(s_w + kk * HD + 4 * tx);
            ulonglong2 bB = *(const ulonglong2*)(s_w + kk * HD + 64 + 4 * tx);
            float av[8] = {a0.x, a0.y, a0.z, a0.w, a1.x, a1.y, a1.z, a1.w};
#pragma unroll
            for (int r = 0; r < 8; r++) {
                u64 ar = pack2(av[r]);
                FMA2(acc[r][0], ar, bA.x);
                FMA2(acc[r][1], ar, bA.y);
                FMA2(acc[r][2], ar, bB.x);
                FMA2(acc[r][3], ar, bB.y);
            }
        }
    }

    __syncthreads();                            // part-A A-reads done

    // ---- stage A part 2: ch 0..63 = m_i ch 64..127 ----
#pragma unroll
    for (int it = 0; it < 8; it++) {
        int idx = it * 256 + tid;               // 2048 float4 items
        int k = idx & 63;
        int nl = idx >> 6;
        int node = n0 + nl; if (node >= N) node = N - 1;
        float4 v = *(const float4*)(g_mi + ((size_t)node * HD + HH + k) * T);
        *(float4*)(s_buf + k * STRIDE + nl * 4) = v;
    }

    // part B: 2 chunks over nw1 rows 128..191 (prefetched pre holds rows 128..159)
#pragma unroll 1
    for (int kc = 0; kc < 2; kc++) {
        __syncthreads();
#pragma unroll
        for (int i = 0; i < 4; i++)
            *(float4*)(s_w + i * 1024 + tid * 4) = pre[i];
        __syncthreads();
        if (kc == 0) {
#pragma unroll
            for (int i = 0; i < 4; i++) {
                int off = i * 1024 + tid * 4;
                pre[i] = *(const float4*)(nw1 + (160 + (off >> 7)) * HD + (off & 127));
            }
        }
        const float* ap = s_buf + (kc * 32) * STRIDE + ty * 8;
#pragma unroll 8
        for (int kk = 0; kk < 32; kk++) {
            float4 a0 = *(const float4*)(ap);
            float4 a1 = *(const float4*)(ap + 4);
            ap += STRIDE;
            ulonglong2 bA = *(const ulonglong2*)(s_w + kk * HD + 4 * tx);
            ulonglong2 bB = *(const ulonglong2*)(s_w + kk * HD + 64 + 4 * tx);
            float av[8] = {a0.x, a0.y, a0.z, a0.w, a1.x, a1.y, a1.z, a1.w};
#pragma unroll
            for (int r = 0; r < 8; r++) {
                u64 ar = pack2(av[r]);
                FMA2(acc[r][0], ar, bA.x);
                FMA2(acc[r][1], ar, bA.y);
                FMA2(acc[r][2], ar, bB.x);
                FMA2(acc[r][3], ar, bB.y);
            }
        }
    }

    // finalize layer 1 (silu)
    float o1[8][8];
#pragma unroll
    for (int r = 0; r < 8; r++)
#pragma unroll
        for (int cp = 0; cp < 4; cp++) {
            float lo, hi; unpack2(acc[r][cp], lo, hi);
            o1[r][2 * cp]     = silu_f(lo);
            o1[r][2 * cp + 1] = silu_f(hi);
        }

    __syncthreads();                            // part-B A-reads done
    // ---- restage o1 (128 ch) into s_buf channel-major ----
#pragma unroll
    for (int c = 0; c < 8; c++) {
        int col = (c < 4) ? 4 * tx + c : 60 + 4 * tx + c;
        *(float4*)(s_buf + col * STRIDE + ty * 8) =
            make_float4(o1[0][c], o1[1][c], o1[2][c], o1[3][c]);
        *(float4*)(s_buf + col * STRIDE + ty * 8 + 4) =
            make_float4(o1[4][c], o1[5][c], o1[6][c], o1[7][c]);
    }

    // ---- layer 2: 128 -> 64, linear; thread covers cols 4tx..4tx+3 ----
    u64 acc2[8][2];
    {
        float4 b = *(const float4*)(nb2 + 4 * tx);
        u64 i0 = packab(b.x, b.y), i1 = packab(b.z, b.w);
#pragma unroll
        for (int r = 0; r < 8; r++) { acc2[r][0] = i0; acc2[r][1] = i1; }
    }
    float4 pre2[2];
#pragma unroll
    for (int i = 0; i < 2; i++) {
        int off = i * 1024 + tid * 4;
        pre2[i] = *(const float4*)(nw2 + (off >> 6) * HH + (off & 63));
    }
#pragma unroll 1
    for (int kc = 0; kc < 4; kc++) {
        __syncthreads();
#pragma unroll
        for (int i = 0; i < 2; i++)
            *(float4*)(s_w + i * 1024 + tid * 4) = pre2[i];
        __syncthreads();
        if (kc < 3) {
#pragma unroll
            for (int i = 0; i < 2; i++) {
                int off = i * 1024 + tid * 4;
                pre2[i] = *(const float4*)(nw2 + ((kc + 1) * 32 + (off >> 6)) * HH + (off & 63));
            }
        }
        const float* ap = s_buf + (kc * 32) * STRIDE + ty * 8;
#pragma unroll 8
        for (int kk = 0; kk < 32; kk++) {
            float4 a0 = *(const float4*)(ap);
            float4 a1 = *(const float4*)(ap + 4);
            ap += STRIDE;
            ulonglong2 w01 = *(const ulonglong2*)(s_w + kk * HH + 4 * tx);
            float av[8] = {a0.x, a0.y, a0.z, a0.w, a1.x, a1.y, a1.z, a1.w};
#pragma unroll
            for (int r = 0; r < 8; r++) {
                u64 ar = pack2(av[r]);
                FMA2(acc2[r][0], ar, w01.x);
                FMA2(acc2[r][1], ar, w01.y);
            }
        }
    }

    // ---- write h_new: rows ty*8+r -> node n0+2ty+(r>>2), t=r&3 ----
    float o2[8][4];
#pragma unroll
    for (int r = 0; r < 8; r++) {
        unpack2(acc2[r][0], o2[r][0], o2[r][1]);
        unpack2(acc2[r][1], o2[r][2], o2[r][3]);
    }
#pragma unroll
    for (int half = 0; half < 2; half++) {
        int n = n0 + 2 * ty + half;
        if (n < N) {
#pragma unroll
            for (int c = 0; c < 4; c++) {
                int col = 4 * tx + c;
                *(float4*)(out_h + ((size_t)n * HH + col) * T) =
                    make_float4(o2[half * 4 + 0][c], o2[half * 4 + 1][c],
                                o2[half * 4 + 2][c], o2[half * 4 + 3][c]);
            }
        }
    }
}

extern "C" void kernel_launch(void* const* d_in, const int* in_sizes, int n_in,
                              void* d_out, int out_size)
{
    const float* x   = (const float*)d_in[0];
    const float* h   = (const float*)d_in[1];
    const int*   ei  = (const int*)  d_in[2];
    const float* ea  = (const float*)d_in[3];
    const float* ew1 = (const float*)d_in[5];
    const float* eb1 = (const float*)d_in[6];
    const float* ew2 = (const float*)d_in[7];
    const float* eb2 = (const float*)d_in[8];
    const float* cw1 = (const float*)d_in[9];
    const float* cb1 = (const float*)d_in[10];
    const float* cw2 = (const float*)d_in[11];
    const float* cb2 = (const float*)d_in[12];
    const float* nw1 = (const float*)d_in[13];
    const float* nb1 = (const float*)d_in[14];
    const float* nw2 = (const float*)d_in[15];
    const float* nb2 = (const float*)d_in[16];

    int N = in_sizes[0] / (3 * T);
    int E = in_sizes[3] / (HE * T);

    float* out_x = (float*)d_out;
    float* out_h = out_x + (size_t)N * 3 * T;

    const int pre_smem  = (HH * STRIDE + 32 * HD) * sizeof(float);
    const int edge_smem = ((HD + HE) * STRIDE + 32 * HD) * sizeof(float);
    const int node_smem = (HD * STRIDE + 32 * HD) * sizeof(float);
    cudaFuncSetAttribute(pre_kernel, cudaFuncAttributeMaxDynamicSharedMemorySize,
                         pre_smem);
    cudaFuncSetAttribute(edge_kernel, cudaFuncAttributeMaxDynamicSharedMemorySize,
                         edge_smem);
    cudaFuncSetAttribute(node_kernel, cudaFuncAttributeMaxDynamicSharedMemorySize,
                         node_smem);

    zero_kernel<<<2048, 256>>>(N);
    pre_kernel<<<(N + NPRE - 1) / NPRE, 256, pre_smem>>>(h, ew1, N);
    edge_kernel<<<(E + EPB - 1) / EPB, 256, edge_smem>>>(
        x, ei, ea, ew1, eb1, ew2, eb2, cw1, cb1, cw2, cb2, E);
    node_kernel<<<(N + NPB - 1) / NPB, 256, node_smem>>>(
        x, h, nw1, nb1, nw2, nb2, out_x, out_h, N);
}

// round 9
// speedup vs baseline: 3.7947x; 1.0936x over previous
#include <cuda_runtime.h>

#define T    4
#define HH   64
#define HE   16
#define HD   128
#define EPB  32          // edges per edge-block
#define ROWS 128         // EPB*T rows per block
#define STRIDE 132       // padded row length (floats) in A buffer
#define NPRE 32          // nodes per precompute block
#define NPB  32          // nodes per node-block (128 rows)
#define MAXN 20000
#define EPSF 1e-8f

typedef unsigned long long u64;

// Scratch (device globals — no allocation allowed; zero-init .bss)
__device__ float g_mi[MAXN * HD * T];    // segment-summed m_ij  [N,HD,T]
__device__ float g_agg[MAXN * 3 * T];    // coord aggregate      [N,3,T]
__device__ float g_cnt[MAXN];            // edge counts          [N]
__device__ float g_p1[(size_t)MAXN * T * HD];  // h[n] @ W1[0:64]   [N,T,HD]
__device__ float g_p2[(size_t)MAXN * T * HD];  // h[n] @ W1[64:128] [N,T,HD]
__device__ float g_zerobias[HD];         // stays zero

// silu via approximate reciprocal (MUFU.RCP + FMUL instead of IEEE div's
// ~15-inst Newton chain). rel err ~2^-21 — invisible at our 1e-3 threshold.
__device__ __forceinline__ float silu_f(float v) {
    return v * __fdividef(1.0f, 1.0f + __expf(-v));
}

// packed fp32x2 FMA: d = a*b + d  (Blackwell FFMA2)
#define FMA2(d, a, b) asm("fma.rn.f32x2 %0, %1, %2, %0;" : "+l"(d) : "l"(a), "l"(b))

__device__ __forceinline__ u64 packab(float a, float b) {
    u64 r; asm("mov.b64 %0, {%1, %2};" : "=l"(r) : "f"(a), "f"(b)); return r;
}
__device__ __forceinline__ u64 pack2(float v) { return packab(v, v); }
__device__ __forceinline__ void unpack2(u64 v, float& lo, float& hi) {
    asm("mov.b64 {%0, %1}, %2;" : "=f"(lo), "=f"(hi) : "l"(v));
}

// ---------------------------------------------------------------------------
// Round-3 register-tiled GEMM phase over a 128-row x 128-col tile.
// Thread (ty 0..15, tx 0..15): rows ty*8..+7; cols {4tx..4tx+3, 64+4tx..+3}.
// out[r][c]: c 0..3 -> col 4tx+c ; c 4..7 -> col 60+4tx+c.
// ---------------------------------------------------------------------------
template<int NCHUNK, int KLIM, bool ACT>
__device__ __forceinline__ void gemm_phase(
    const float* __restrict__ sA, float* __restrict__ sW,
    const float* __restrict__ gW, const float* __restrict__ gB,
    int tid, int tx, int ty, float (&out)[8][8])
{
    u64 acc[8][4];
    {
        float4 bA = *(const float4*)(gB + 4 * tx);
        float4 bB = *(const float4*)(gB + 64 + 4 * tx);
        u64 i0 = packab(bA.x, bA.y), i1 = packab(bA.z, bA.w);
        u64 i2 = packab(bB.x, bB.y), i3 = packab(bB.z, bB.w);
#pragma unroll
        for (int r = 0; r < 8; r++) {
            acc[r][0] = i0; acc[r][1] = i1; acc[r][2] = i2; acc[r][3] = i3;
        }
    }

    float4 pre[4];
#pragma unroll
    for (int i = 0; i < 4; i++) {
        int off = i * 1024 + tid * 4;
        int kg = off >> 7;
        pre[i] = (kg < KLIM) ? *(const float4*)(gW + kg * HD + (off & 127))
                             : make_float4(0.f, 0.f, 0.f, 0.f);
    }

#pragma unroll 1
    for (int kc = 0; kc < NCHUNK; kc++) {
        __syncthreads();                       // prev chunk consumers done
#pragma unroll
        for (int i = 0; i < 4; i++)
            *(float4*)(sW + i * 1024 + tid * 4) = pre[i];
        __syncthreads();
        if (kc + 1 < NCHUNK) {
#pragma unroll
            for (int i = 0; i < 4; i++) {
                int off = i * 1024 + tid * 4;
                int kg = (kc + 1) * 32 + (off >> 7);
                pre[i] = (kg < KLIM) ? *(const float4*)(gW + kg * HD + (off & 127))
                                     : make_float4(0.f, 0.f, 0.f, 0.f);
            }
        }
        const float* ap = sA + (kc * 32) * STRIDE + ty * 8;
#pragma unroll 8
        for (int kk = 0; kk < 32; kk++) {
            float4 a0 = *(const float4*)(ap);
            float4 a1 = *(const float4*)(ap + 4);
            ap += STRIDE;
            ulonglong2 bA = *(const ulonglong2*)(sW + kk * HD + 4 * tx);
            ulonglong2 bB = *(const ulonglong2*)(sW + kk * HD + 64 + 4 * tx);
            float av[8] = {a0.x, a0.y, a0.z, a0.w, a1.x, a1.y, a1.z, a1.w};
#pragma unroll
            for (int r = 0; r < 8; r++) {
                u64 ar = pack2(av[r]);
                FMA2(acc[r][0], ar, bA.x);
                FMA2(acc[r][1], ar, bA.y);
                FMA2(acc[r][2], ar, bB.x);
                FMA2(acc[r][3], ar, bB.y);
            }
        }
    }

#pragma unroll
    for (int r = 0; r < 8; r++)
#pragma unroll
        for (int cp = 0; cp < 4; cp++) {
            float lo, hi; unpack2(acc[r][cp], lo, hi);
            out[r][cp * 2]     = ACT ? silu_f(lo) : lo;
            out[r][cp * 2 + 1] = ACT ? silu_f(hi) : hi;
        }
}

__global__ void zero_kernel(int n) {
    int stride = gridDim.x * blockDim.x;
    int base = blockIdx.x * blockDim.x + threadIdx.x;
    for (int i = base; i < n * HD * T; i += stride) g_mi[i] = 0.0f;
    for (int i = base; i < n * 3 * T;  i += stride) g_agg[i] = 0.0f;
    for (int i = base; i < n;          i += stride) g_cnt[i] = 0.0f;
}

// ---------------------------------------------------------------------------
// Precompute P1 = h @ W1[0:64], P2 = h @ W1[64:128] per node (80k rows).
// ---------------------------------------------------------------------------
__global__ __launch_bounds__(256, 2) void pre_kernel(
    const float* __restrict__ h, const float* __restrict__ w1, int N)
{
    extern __shared__ float sm[];
    float* s_h = sm;                           // 64 * STRIDE
    float* s_w = sm + HH * STRIDE;             // 32 * HD

    const int tid = threadIdx.x;
    const int tx  = tid & 15;
    const int ty  = tid >> 4;
    const int n0  = blockIdx.x * NPRE;

#pragma unroll
    for (int it = 0; it < 8; it++) {
        int idx = it * 256 + tid;              // 2048 float4 items
        int k = idx & 63;
        int nl = idx >> 6;
        int node = n0 + nl; if (node >= N) node = N - 1;
        float4 v = *(const float4*)(h + ((size_t)node * HH + k) * T);
        *(float4*)(s_h + k * STRIDE + nl * 4) = v;
    }
    // (gemm_phase's first __syncthreads covers gather->compute ordering)

    float o[8][8];
    gemm_phase<2, HH, false>(s_h, s_w, w1, g_zerobias, tid, tx, ty, o);
#pragma unroll
    for (int r = 0; r < 8; r++) {
        int row = ty * 8 + r;
        int node = n0 + (row >> 2), t = row & 3;
        if (node < N) {
            float* p = g_p1 + ((size_t)node * T + t) * HD;
            *(float4*)(p + 4 * tx)      = make_float4(o[r][0], o[r][1], o[r][2], o[r][3]);
            *(float4*)(p + 64 + 4 * tx) = make_float4(o[r][4], o[r][5], o[r][6], o[r][7]);
        }
    }

    gemm_phase<2, HH, false>(s_h, s_w, w1 + HH * HD, g_zerobias, tid, tx, ty, o);
#pragma unroll
    for (int r = 0; r < 8; r++) {
        int row = ty * 8 + r;
        int node = n0 + (row >> 2), t = row & 3;
        if (node < N) {
            float* p = g_p2 + ((size_t)node * T + t) * HD;
            *(float4*)(p + 4 * tx)      = make_float4(o[r][0], o[r][1], o[r][2], o[r][3]);
            *(float4*)(p + 64 + 4 * tx) = make_float4(o[r][4], o[r][5], o[r][6], o[r][7]);
        }
    }
}

// ---------------------------------------------------------------------------
// Edge kernel (round-7 structure; silu now approx-div)
// ---------------------------------------------------------------------------
__global__ __launch_bounds__(256, 2) void edge_kernel(
    const float* __restrict__ x,
    const int* __restrict__ ei, const float* __restrict__ ea,
    const float* __restrict__ w1, const float* __restrict__ b1,
    const float* __restrict__ w2, const float* __restrict__ b2,
    const float* __restrict__ cw1, const float* __restrict__ cb1,
    const float* __restrict__ cw2, const float* __restrict__ cb2,
    int E)
{
    extern __shared__ float sm[];
    float* s_buf = sm;                         // 128 * STRIDE (mid / m_ij)
    float* s_ea  = sm + HD * STRIDE;           // 16 * STRIDE
    float* s_w   = s_ea + HE * STRIDE;         // 32 * HD
    float* s_part = s_buf;                     // 16*ROWS, overlays s_buf late

    __shared__ int   s_rown[EPB], s_coln[EPB];
    __shared__ float s_xij[EPB][3][T];
    __shared__ float s_n2[ROWS];

    const int tid = threadIdx.x;
    const int tx  = tid & 15;
    const int ty  = tid >> 4;
    const int e0  = blockIdx.x * EPB;

    if (tid < EPB) {
        int eg = e0 + tid;
        if (eg >= E) eg = E - 1;
        s_rown[tid] = ei[eg];
        s_coln[tid] = ei[E + eg];
    }

    // ---- stage W1 rows 129..144 (ea part) + row 128 (n2 weights) into s_w ----
    for (int i = tid; i < 17 * 32; i += 256) {
        int k = i >> 5, cg = i & 31;
        int srcrow = (k == 16) ? 128 : (129 + k);
        *(float4*)(s_w + k * HD + cg * 4) = *(const float4*)(w1 + srcrow * HD + cg * 4);
    }
    __syncthreads();                           // s_rown/s_coln ready too

    // ---- edge_attr gather: 16 ch x 32 edges, float4 over t ----
#pragma unroll
    for (int it = 0; it < 2; it++) {
        int idx = it * 256 + tid;              // 512 items
        int k = idx & 15;
        int e = idx >> 4;
        int eg = e0 + e; if (eg >= E) eg = E - 1;
        float4 v = *(const float4*)(ea + ((size_t)eg * HE + k) * T);
        *(float4*)(s_ea + k * STRIDE + e * 4) = v;
    }
    // ---- x_ij, n2 ----
    if (tid < ROWS) {
        int e = tid >> 2, t = tid & 3;
        int rn = s_rown[e], cn = s_coln[e];
        float n2 = 0.f;
#pragma unroll
        for (int d = 0; d < 3; d++) {
            float v = x[((size_t)rn * 3 + d) * T + t] - x[((size_t)cn * 3 + d) * T + t];
            s_xij[e][d][t] = v;
            n2 += v * v;
        }
        s_n2[tid] = n2;
    }
    __syncthreads();

    // ---- layer 1 ----
    float o1[8][8];
    {
        u64 acc[8][4];
        float4 bA = *(const float4*)(b1 + 4 * tx);
        float4 bB = *(const float4*)(b1 + 64 + 4 * tx);
        float4 wA = *(const float4*)(s_w + 16 * HD + 4 * tx);
        float4 wB = *(const float4*)(s_w + 16 * HD + 64 + 4 * tx);
#pragma unroll
        for (int r = 0; r < 8; r++) {
            int row = ty * 8 + r;
            int e = row >> 2, t = row & 3;
            const float* p1 = g_p1 + ((size_t)s_rown[e] * T + t) * HD;
            const float* p2 = g_p2 + ((size_t)s_coln[e] * T + t) * HD;
            float4 a1 = *(const float4*)(p1 + 4 * tx);
            float4 c1 = *(const float4*)(p1 + 64 + 4 * tx);
            float4 a2 = *(const float4*)(p2 + 4 * tx);
            float4 c2 = *(const float4*)(p2 + 64 + 4 * tx);
            float n2r = s_n2[row];
            float v0 = bA.x + a1.x + a2.x + n2r * wA.x;
            float v1 = bA.y + a1.y + a2.y + n2r * wA.y;
            float v2 = bA.z + a1.z + a2.z + n2r * wA.z;
            float v3 = bA.w + a1.w + a2.w + n2r * wA.w;
            float v4 = bB.x + c1.x + c2.x + n2r * wB.x;
            float v5 = bB.y + c1.y + c2.y + n2r * wB.y;
            float v6 = bB.z + c1.z + c2.z + n2r * wB.z;
            float v7 = bB.w + c1.w + c2.w + n2r * wB.w;
            acc[r][0] = packab(v0, v1); acc[r][1] = packab(v2, v3);
            acc[r][2] = packab(v4, v5); acc[r][3] = packab(v6, v7);
        }
        const float* ap = s_ea + ty * 8;
#pragma unroll
        for (int k = 0; k < HE; k++) {
            float4 a0 = *(const float4*)(ap);
            float4 a1 = *(const float4*)(ap + 4);
            ap += STRIDE;
            ulonglong2 wp0 = *(const ulonglong2*)(s_w + k * HD + 4 * tx);
            ulonglong2 wp1 = *(const ulonglong2*)(s_w + k * HD + 64 + 4 * tx);
            float av[8] = {a0.x, a0.y, a0.z, a0.w, a1.x, a1.y, a1.z, a1.w};
#pragma unroll
            for (int r = 0; r < 8; r++) {
                u64 ar = pack2(av[r]);
                FMA2(acc[r][0], ar, wp0.x);
                FMA2(acc[r][1], ar, wp0.y);
                FMA2(acc[r][2], ar, wp1.x);
                FMA2(acc[r][3], ar, wp1.y);
            }
        }
#pragma unroll
        for (int r = 0; r < 8; r++)
#pragma unroll
            for (int cp = 0; cp < 4; cp++) {
                float lo, hi; unpack2(acc[r][cp], lo, hi);
                o1[r][2 * cp]     = silu_f(lo);
                o1[r][2 * cp + 1] = silu_f(hi);
            }
    }
    __syncthreads();                           // s_w readers done (before restage)

    // ---- mid -> s_buf ----
#pragma unroll
    for (int c = 0; c < 8; c++) {
        int col = (c < 4) ? 4 * tx + c : 60 + 4 * tx + c;
        *(float4*)(s_buf + col * STRIDE + ty * 8) =
            make_float4(o1[0][c], o1[1][c], o1[2][c], o1[3][c]);
        *(float4*)(s_buf + col * STRIDE + ty * 8 + 4) =
            make_float4(o1[4][c], o1[5][c], o1[6][c], o1[7][c]);
    }

    // ---- layer 2: m_ij = silu(mid @ W2 + b2) ----
    float o2[8][8];
    gemm_phase<4, HD, true>(s_buf, s_w, w2, b2, tid, tx, ty, o2);

    // ---- scatter m_i ----
#pragma unroll
    for (int eh = 0; eh < 2; eh++) {
        int el = 2 * ty + eh;
        if (e0 + el < E) {
            int node = s_rown[el];
#pragma unroll
            for (int c = 0; c < 8; c++) {
                int col = (c < 4) ? 4 * tx + c : 60 + 4 * tx + c;
                float* p = &g_mi[((size_t)node * HD + col) * T];
                asm volatile("red.global.add.v4.f32 [%0], {%1,%2,%3,%4};"
                             :: "l"(p), "f"(o2[eh * 4 + 0][c]), "f"(o2[eh * 4 + 1][c]),
                                "f"(o2[eh * 4 + 2][c]), "f"(o2[eh * 4 + 3][c])
                             : "memory");
            }
        }
    }

    // ---- m_ij -> smem for coord MLP ----
    __syncthreads();
#pragma unroll
    for (int c = 0; c < 8; c++) {
        int col = (c < 4) ? 4 * tx + c : 60 + 4 * tx + c;
        *(float4*)(s_buf + col * STRIDE + ty * 8) =
            make_float4(o2[0][c], o2[1][c], o2[2][c], o2[3][c]);
        *(float4*)(s_buf + col * STRIDE + ty * 8 + 4) =
            make_float4(o2[4][c], o2[5][c], o2[6][c], o2[7][c]);
    }

    // ---- coord layer 1: silu(m_ij @ cw1 + cb1) ----
    float o3[8][8];
    gemm_phase<4, HD, true>(s_buf, s_w, cw1, cb1, tid, tx, ty, o3);

    // ---- coord projection to 1: partials ----
    {
        float4 c2a = *(const float4*)(cw2 + 4 * tx);
        float4 c2b = *(const float4*)(cw2 + 64 + 4 * tx);
        float cw[8] = {c2a.x, c2a.y, c2a.z, c2a.w, c2b.x, c2b.y, c2b.z, c2b.w};
        float p[8];
#pragma unroll
        for (int r = 0; r < 8; r++) {
            float s = 0.f;
#pragma unroll
            for (int c = 0; c < 8; c++) s += o3[r][c] * cw[c];
            p[r] = s;
        }
        __syncthreads();                       // s_buf reads (GEMM3) done
        *(float4*)(s_part + tx * ROWS + ty * 8) = make_float4(p[0], p[1], p[2], p[3]);
        *(float4*)(s_part + tx * ROWS + ty * 8 + 4) = make_float4(p[4], p[5], p[6], p[7]);
    }
    __syncthreads();

    if (tid < ROWS) {
        float cval = cb2[0];
#pragma unroll
        for (int q = 0; q < 16; q++) cval += s_part[q * ROWS + tid];
        cval *= __fdividef(1.0f, sqrtf(s_n2[tid] + EPSF) + 1.0f);
        int e = tid >> 2, t = tid & 3;
        if (e0 + e < E) {
            int node = s_rown[e];
#pragma unroll
            for (int d = 0; d < 3; d++)
                atomicAdd(&g_agg[((size_t)node * 3 + d) * T + t], cval * s_xij[e][d][t]);
            if (t == 0) atomicAdd(&g_cnt[node], 1.0f);
        }
    }
}

// ---------------------------------------------------------------------------
// Node kernel (round-8 register-tiled version; silu now approx-div)
// ---------------------------------------------------------------------------
__global__ __launch_bounds__(256, 2) void node_kernel(
    const float* __restrict__ x, const float* __restrict__ h,
    const float* __restrict__ nw1, const float* __restrict__ nb1,
    const float* __restrict__ nw2, const float* __restrict__ nb2,
    float* __restrict__ out_x, float* __restrict__ out_h, int N)
{
    extern __shared__ float sm[];
    float* s_buf = sm;                         // 128 ch * STRIDE
    float* s_w   = sm + HD * STRIDE;           // 32 * HD

    const int tid = threadIdx.x;
    const int tx  = tid & 15;
    const int ty  = tid >> 4;
    const int n0  = blockIdx.x * NPB;

    // ---- x_new epilogue: 32 nodes * 12 = 384 items ----
#pragma unroll
    for (int it = 0; it < 2; it++) {
        int idx = it * 256 + tid;
        if (idx < NPB * 12) {
            int n = n0 + idx / 12;
            if (n < N) {
                int rem = idx % 12, d = rem >> 2, t = rem & 3;
                float cv = fmaxf(g_cnt[n], 1.0f);
                int off = (n * 3 + d) * T + t;
                out_x[off] = x[off] + g_agg[off] * __fdividef(1.0f, cv);
            }
        }
    }

    // ---- stage A part 1: ch 0..127 = [h(64) | m_i ch 0..63] ----
#pragma unroll
    for (int it = 0; it < 16; it++) {
        int idx = it * 256 + tid;              // 4096 float4 items
        int k = idx & 127;
        int nl = idx >> 7;
        int node = n0 + nl; if (node >= N) node = N - 1;
        float4 v = (k < HH)
            ? *(const float4*)(h    + ((size_t)node * HH + k) * T)
            : *(const float4*)(g_mi + ((size_t)node * HD + (k - HH)) * T);
        *(float4*)(s_buf + k * STRIDE + nl * 4) = v;
    }

    // ---- layer 1: acc over k 0..191 in two A-stages ----
    u64 acc[8][4];
    {
        float4 bA = *(const float4*)(nb1 + 4 * tx);
        float4 bB = *(const float4*)(nb1 + 64 + 4 * tx);
        u64 i0 = packab(bA.x, bA.y), i1 = packab(bA.z, bA.w);
        u64 i2 = packab(bB.x, bB.y), i3 = packab(bB.z, bB.w);
#pragma unroll
        for (int r = 0; r < 8; r++) {
            acc[r][0] = i0; acc[r][1] = i1; acc[r][2] = i2; acc[r][3] = i3;
        }
    }

    float4 pre[4];
#pragma unroll
    for (int i = 0; i < 4; i++) {
        int off = i * 1024 + tid * 4;
        pre[i] = *(const float4*)(nw1 + (off >> 7) * HD + (off & 127));
    }

    // part A: 4 chunks over nw1 rows 0..127
#pragma unroll 1
    for (int kc = 0; kc < 4; kc++) {
        __syncthreads();
#pragma unroll
        for (int i = 0; i < 4; i++)
            *(float4*)(s_w + i * 1024 + tid * 4) = pre[i];
        __syncthreads();
        {
            int kbase = (kc + 1) * 32;          // rows 32..191 (valid: 192 total)
            if (kbase < 192) {
#pragma unroll
                for (int i = 0; i < 4; i++) {
                    int off = i * 1024 + tid * 4;
                    pre[i] = *(const float4*)(nw1 + (kbase + (off >> 7)) * HD + (off & 127));
                }
            }
        }
        const float* ap = s_buf + (kc * 32) * STRIDE + ty * 8;
#pragma unroll 8
        for (int kk = 0; kk < 32; kk++) {
            float4 a0 = *(const float4*)(ap);
            float4 a1 = *(const float4*)(ap + 4);
            ap += STRIDE;
            ulonglong2 bA = *(const ulonglong2*)(s_w + kk * HD + 4 * tx);
            ulonglong2 bB = *(const ulonglong2*)(s_w + kk * HD + 64 + 4 * tx);
            float av[8] = {a0.x, a0.y, a0.z, a0.w, a1.x, a1.y, a1.z, a1.w};
#pragma unroll
            for (int r = 0; r < 8; r++) {
                u64 ar = pack2(av[r]);
                FMA2(acc[r][0], ar, bA.x);
                FMA2(acc[r][1], ar, bA.y);
                FMA2(acc[r][2], ar, bB.x);
                FMA2(acc[r][3], ar, bB.y);
            }
        }
    }

    __syncthreads();                            // part-A A-reads done

    // ---- stage A part 2: ch 0..63 = m_i ch 64..127 ----
#pragma unroll
    for (int it = 0; it < 8; it++) {
        int idx = it * 256 + tid;               // 2048 float4 items
        int k = idx & 63;
        int nl = idx >> 6;
        int node = n0 + nl; if (node >= N) node = N - 1;
        float4 v = *(const float4*)(g_mi + ((size_t)node * HD + HH + k) * T);
        *(float4*)(s_buf + k * STRIDE + nl * 4) = v;
    }

    // part B: 2 chunks over nw1 rows 128..191 (prefetched pre holds rows 128..159)
#pragma unroll 1
    for (int kc = 0; kc < 2; kc++) {
        __syncthreads();
#pragma unroll
        for (int i = 0; i < 4; i++)
            *(float4*)(s_w + i * 1024 + tid * 4) = pre[i];
        __syncthreads();
        if (kc == 0) {
#pragma unroll
            for (int i = 0; i < 4; i++) {
                int off = i * 1024 + tid * 4;
                pre[i] = *(const float4*)(nw1 + (160 + (off >> 7)) * HD + (off & 127));
            }
        }
        const float* ap = s_buf + (kc * 32) * STRIDE + ty * 8;
#pragma unroll 8
        for (int kk = 0; kk < 32; kk++) {
            float4 a0 = *(const float4*)(ap);
            float4 a1 = *(const float4*)(ap + 4);
            ap += STRIDE;
            ulonglong2 bA = *(const ulonglong2*)(s_w + kk * HD + 4 * tx);
            ulonglong2 bB = *(const ulonglong2*)(s_w + kk * HD + 64 + 4 * tx);
            float av[8] = {a0.x, a0.y, a0.z, a0.w, a1.x, a1.y, a1.z, a1.w};
#pragma unroll
            for (int r = 0; r < 8; r++) {
                u64 ar = pack2(av[r]);
                FMA2(acc[r][0], ar, bA.x);
                FMA2(acc[r][1], ar, bA.y);
                FMA2(acc[r][2], ar, bB.x);
                FMA2(acc[r][3], ar, bB.y);
            }
        }
    }

    // finalize layer 1 (silu)
    float o1[8][8];
#pragma unroll
    for (int r = 0; r < 8; r++)
#pragma unroll
        for (int cp = 0; cp < 4; cp++) {
            float lo, hi; unpack2(acc[r][cp], lo, hi);
            o1[r][2 * cp]     = silu_f(lo);
            o1[r][2 * cp + 1] = silu_f(hi);
        }

    __syncthreads();                            // part-B A-reads done
    // ---- restage o1 (128 ch) into s_buf channel-major ----
#pragma unroll
    for (int c = 0; c < 8; c++) {
        int col = (c < 4) ? 4 * tx + c : 60 + 4 * tx + c;
        *(float4*)(s_buf + col * STRIDE + ty * 8) =
            make_float4(o1[0][c], o1[1][c], o1[2][c], o1[3][c]);
        *(float4*)(s_buf + col * STRIDE + ty * 8 + 4) =
            make_float4(o1[4][c], o1[5][c], o1[6][c], o1[7][c]);
    }

    // ---- layer 2: 128 -> 64, linear; thread covers cols 4tx..4tx+3 ----
    u64 acc2[8][2];
    {
        float4 b = *(const float4*)(nb2 + 4 * tx);
        u64 i0 = packab(b.x, b.y), i1 = packab(b.z, b.w);
#pragma unroll
        for (int r = 0; r < 8; r++) { acc2[r][0] = i0; acc2[r][1] = i1; }
    }
    float4 pre2[2];
#pragma unroll
    for (int i = 0; i < 2; i++) {
        int off = i * 1024 + tid * 4;
        pre2[i] = *(const float4*)(nw2 + (off >> 6) * HH + (off & 63));
    }
#pragma unroll 1
    for (int kc = 0; kc < 4; kc++) {
        __syncthreads();
#pragma unroll
        for (int i = 0; i < 2; i++)
            *(float4*)(s_w + i * 1024 + tid * 4) = pre2[i];
        __syncthreads();
        if (kc < 3) {
#pragma unroll
            for (int i = 0; i < 2; i++) {
                int off = i * 1024 + tid * 4;
                pre2[i] = *(const float4*)(nw2 + ((kc + 1) * 32 + (off >> 6)) * HH + (off & 63));
            }
        }
        const float* ap = s_buf + (kc * 32) * STRIDE + ty * 8;
#pragma unroll 8
        for (int kk = 0; kk < 32; kk++) {
            float4 a0 = *(const float4*)(ap);
            float4 a1 = *(const float4*)(ap + 4);
            ap += STRIDE;
            ulonglong2 w01 = *(const ulonglong2*)(s_w + kk * HH + 4 * tx);
            float av[8] = {a0.x, a0.y, a0.z, a0.w, a1.x, a1.y, a1.z, a1.w};
#pragma unroll
            for (int r = 0; r < 8; r++) {
                u64 ar = pack2(av[r]);
                FMA2(acc2[r][0], ar, w01.x);
                FMA2(acc2[r][1], ar, w01.y);
            }
        }
    }

    // ---- write h_new: rows ty*8+r -> node n0+2ty+(r>>2), t=r&3 ----
    float o2[8][4];
#pragma unroll
    for (int r = 0; r < 8; r++) {
        unpack2(acc2[r][0], o2[r][0], o2[r][1]);
        unpack2(acc2[r][1], o2[r][2], o2[r][3]);
    }
#pragma unroll
    for (int half = 0; half < 2; half++) {
        int n = n0 + 2 * ty + half;
        if (n < N) {
#pragma unroll
            for (int c = 0; c < 4; c++) {
                int col = 4 * tx + c;
                *(float4*)(out_h + ((size_t)n * HH + col) * T) =
                    make_float4(o2[half * 4 + 0][c], o2[half * 4 + 1][c],
                                o2[half * 4 + 2][c], o2[half * 4 + 3][c]);
            }
        }
    }
}

extern "C" void kernel_launch(void* const* d_in, const int* in_sizes, int n_in,
                              void* d_out, int out_size)
{
    const float* x   = (const float*)d_in[0];
    const float* h   = (const float*)d_in[1];
    const int*   ei  = (const int*)  d_in[2];
    const float* ea  = (const float*)d_in[3];
    const float* ew1 = (const float*)d_in[5];
    const float* eb1 = (const float*)d_in[6];
    const float* ew2 = (const float*)d_in[7];
    const float* eb2 = (const float*)d_in[8];
    const float* cw1 = (const float*)d_in[9];
    const float* cb1 = (const float*)d_in[10];
    const float* cw2 = (const float*)d_in[11];
    const float* cb2 = (const float*)d_in[12];
    const float* nw1 = (const float*)d_in[13];
    const float* nb1 = (const float*)d_in[14];
    const float* nw2 = (const float*)d_in[15];
    const float* nb2 = (const float*)d_in[16];

    int N = in_sizes[0] / (3 * T);
    int E = in_sizes[3] / (HE * T);

    float* out_x = (float*)d_out;
    float* out_h = out_x + (size_t)N * 3 * T;

    const int pre_smem  = (HH * STRIDE + 32 * HD) * sizeof(float);
    const int edge_smem = ((HD + HE) * STRIDE + 32 * HD) * sizeof(float);
    const int node_smem = (HD * STRIDE + 32 * HD) * sizeof(float);
    cudaFuncSetAttribute(pre_kernel, cudaFuncAttributeMaxDynamicSharedMemorySize,
                         pre_smem);
    cudaFuncSetAttribute(edge_kernel, cudaFuncAttributeMaxDynamicSharedMemorySize,
                         edge_smem);
    cudaFuncSetAttribute(node_kernel, cudaFuncAttributeMaxDynamicSharedMemorySize,
                         node_smem);

    zero_kernel<<<2048, 256>>>(N);
    pre_kernel<<<(N + NPRE - 1) / NPRE, 256, pre_smem>>>(h, ew1, N);
    edge_kernel<<<(E + EPB - 1) / EPB, 256, edge_smem>>>(
        x, ei, ea, ew1, eb1, ew2, eb2, cw1, cb1, cw2, cb2, E);
    node_kernel<<<(N + NPB - 1) / NPB, 256, node_smem>>>(
        x, h, nw1, nb1, nw2, nb2, out_x, out_h, N);
}

// round 12
// speedup vs baseline: 4.3913x; 1.1572x over previous
#include <cuda_runtime.h>
#include <cuda_bf16.h>
#include <cstdint>

#define T    4
#define HH   64
#define HE   16
#define HD   128
#define EPB  32
#define ROWS 128
#define STRIDE 132
#define NPRE 32
#define NPB  32
#define MAXN 20000
#define EPSF 1e-8f
#define BROW 272          // bf16 operand row stride in bytes (136 bf16)

typedef unsigned long long u64;
typedef unsigned int u32;

// ---------------- device globals ----------------
__device__ float g_mi[MAXN * T * HD];          // [N, T, HD]
__device__ float g_agg[MAXN * 3 * T];
__device__ float g_cnt[MAXN];
__device__ float g_p1[(size_t)MAXN * T * HD];
__device__ float g_p2[(size_t)MAXN * T * HD];
__device__ float g_zerobias[HD];
// plain [n][k] bf16 hi/lo images of W2^T and CW1^T
__device__ __nv_bfloat16 g_w2hi[HD * HD], g_w2lo[HD * HD];
__device__ __nv_bfloat16 g_c1hi[HD * HD], g_c1lo[HD * HD];

__device__ __forceinline__ float silu_f(float v) {
    return v * __fdividef(1.0f, 1.0f + __expf(-v));
}

#define FMA2(d, a, b) asm("fma.rn.f32x2 %0, %1, %2, %0;" : "+l"(d) : "l"(a), "l"(b))
__device__ __forceinline__ u64 packab(float a, float b) {
    u64 r; asm("mov.b64 %0, {%1, %2};" : "=l"(r) : "f"(a), "f"(b)); return r;
}
__device__ __forceinline__ u64 pack2(float v) { return packab(v, v); }
__device__ __forceinline__ void unpack2(u64 v, float& lo, float& hi) {
    asm("mov.b64 {%0, %1}, %2;" : "=f"(lo), "=f"(hi) : "l"(v));
}
__device__ __forceinline__ u32 smem_u32(const void* p) {
    u32 a;
    asm("{ .reg .u64 t; cvta.to.shared.u64 t, %1; cvt.u32.u64 %0, t; }"
        : "=r"(a) : "l"(p));
    return a;
}
// bf16 pair hi/lo split
__device__ __forceinline__ void split2(float a, float b, u32& h, u32& l) {
    __nv_bfloat162 hp, lp;
    hp.x = __float2bfloat16(a); hp.y = __float2bfloat16(b);
    lp.x = __float2bfloat16(a - __bfloat162float(hp.x));
    lp.y = __float2bfloat16(b - __bfloat162float(hp.y));
    h = *reinterpret_cast<u32*>(&hp);
    l = *reinterpret_cast<u32*>(&lp);
}

#define LDMX4(r0, r1, r2, r3, addr) \
    asm volatile("ldmatrix.sync.aligned.m8n8.x4.shared.b16 {%0,%1,%2,%3}, [%4];" \
        : "=r"(r0), "=r"(r1), "=r"(r2), "=r"(r3) : "r"(addr))

#define MMA16816(d, a0, a1, a2, a3, b0, b1) \
    asm volatile("mma.sync.aligned.m16n8k16.row.col.f32.bf16.bf16.f32 " \
        "{%0,%1,%2,%3}, {%4,%5,%6,%7}, {%8,%9}, {%0,%1,%2,%3};" \
        : "+f"((d)[0]), "+f"((d)[1]), "+f"((d)[2]), "+f"((d)[3]) \
        : "r"(a0), "r"(a1), "r"(a2), "r"(a3), "r"(b0), "r"(b1))

#define REDV2(p, v0, v1) \
    asm volatile("red.global.add.v2.f32 [%0], {%1,%2};" \
                 :: "l"(p), "f"(v0), "f"(v1) : "memory")

// ---------------- small kernels ----------------
__global__ void zero_kernel(int n) {
    int stride = gridDim.x * blockDim.x;
    int base = blockIdx.x * blockDim.x + threadIdx.x;
    for (int i = base; i < n * HD * T; i += stride) g_mi[i] = 0.0f;
    for (int i = base; i < n * 3 * T;  i += stride) g_agg[i] = 0.0f;
    for (int i = base; i < n;          i += stride) g_cnt[i] = 0.0f;
}

// plain [n][k] bf16 hi/lo weight images (B^T: img[n*128+k] = W[k][n])
__global__ void wimg_kernel(const float* __restrict__ w2, const float* __restrict__ cw1) {
    int idx = blockIdx.x * 256 + threadIdx.x;   // 16384
    int n = idx >> 7, k = idx & 127;
    float v2 = w2[k * HD + n];
    __nv_bfloat16 h2 = __float2bfloat16(v2);
    g_w2hi[idx] = h2;
    g_w2lo[idx] = __float2bfloat16(v2 - __bfloat162float(h2));
    float v3 = cw1[k * HD + n];
    __nv_bfloat16 h3 = __float2bfloat16(v3);
    g_c1hi[idx] = h3;
    g_c1lo[idx] = __float2bfloat16(v3 - __bfloat162float(h3));
}

// ---------------- FFMA2 GEMM tile (pre/node kernels) ----------------
template<int NCHUNK, int KLIM, bool ACT>
__device__ __forceinline__ void gemm_phase(
    const float* __restrict__ sA, float* __restrict__ sW,
    const float* __restrict__ gW, const float* __restrict__ gB,
    int tid, int tx, int ty, float (&out)[8][8])
{
    u64 acc[8][4];
    {
        float4 bA = *(const float4*)(gB + 4 * tx);
        float4 bB = *(const float4*)(gB + 64 + 4 * tx);
        u64 i0 = packab(bA.x, bA.y), i1 = packab(bA.z, bA.w);
        u64 i2 = packab(bB.x, bB.y), i3 = packab(bB.z, bB.w);
#pragma unroll
        for (int r = 0; r < 8; r++) {
            acc[r][0] = i0; acc[r][1] = i1; acc[r][2] = i2; acc[r][3] = i3;
        }
    }
    float4 pre[4];
#pragma unroll
    for (int i = 0; i < 4; i++) {
        int off = i * 1024 + tid * 4;
        int kg = off >> 7;
        pre[i] = (kg < KLIM) ? *(const float4*)(gW + kg * HD + (off & 127))
                             : make_float4(0.f, 0.f, 0.f, 0.f);
    }
#pragma unroll 1
    for (int kc = 0; kc < NCHUNK; kc++) {
        __syncthreads();
#pragma unroll
        for (int i = 0; i < 4; i++)
            *(float4*)(sW + i * 1024 + tid * 4) = pre[i];
        __syncthreads();
        if (kc + 1 < NCHUNK) {
#pragma unroll
            for (int i = 0; i < 4; i++) {
                int off = i * 1024 + tid * 4;
                int kg = (kc + 1) * 32 + (off >> 7);
                pre[i] = (kg < KLIM) ? *(const float4*)(gW + kg * HD + (off & 127))
                                     : make_float4(0.f, 0.f, 0.f, 0.f);
            }
        }
        const float* ap = sA + (kc * 32) * STRIDE + ty * 8;
#pragma unroll 8
        for (int kk = 0; kk < 32; kk++) {
            float4 a0 = *(const float4*)(ap);
            float4 a1 = *(const float4*)(ap + 4);
            ap += STRIDE;
            ulonglong2 bA = *(const ulonglong2*)(sW + kk * HD + 4 * tx);
            ulonglong2 bB = *(const ulonglong2*)(sW + kk * HD + 64 + 4 * tx);
            float av[8] = {a0.x, a0.y, a0.z, a0.w, a1.x, a1.y, a1.z, a1.w};
#pragma unroll
            for (int r = 0; r < 8; r++) {
                u64 ar = pack2(av[r]);
                FMA2(acc[r][0], ar, bA.x);
                FMA2(acc[r][1], ar, bA.y);
                FMA2(acc[r][2], ar, bB.x);
                FMA2(acc[r][3], ar, bB.y);
            }
        }
    }
#pragma unroll
    for (int r = 0; r < 8; r++)
#pragma unroll
        for (int cp = 0; cp < 4; cp++) {
            float lo, hi; unpack2(acc[r][cp], lo, hi);
            out[r][cp * 2]     = ACT ? silu_f(lo) : lo;
            out[r][cp * 2 + 1] = ACT ? silu_f(hi) : hi;
        }
}

// ---------------- P1/P2 precompute ----------------
__global__ __launch_bounds__(256, 2) void pre_kernel(
    const float* __restrict__ h, const float* __restrict__ w1, int N)
{
    extern __shared__ float sm[];
    float* s_h = sm;
    float* s_w = sm + HH * STRIDE;
    const int tid = threadIdx.x, tx = tid & 15, ty = tid >> 4;
    const int n0 = blockIdx.x * NPRE;
#pragma unroll
    for (int it = 0; it < 8; it++) {
        int idx = it * 256 + tid;
        int k = idx & 63, nl = idx >> 6;
        int node = n0 + nl; if (node >= N) node = N - 1;
        float4 v = *(const float4*)(h + ((size_t)node * HH + k) * T);
        *(float4*)(s_h + k * STRIDE + nl * 4) = v;
    }
    float o[8][8];
    gemm_phase<2, HH, false>(s_h, s_w, w1, g_zerobias, tid, tx, ty, o);
#pragma unroll
    for (int r = 0; r < 8; r++) {
        int row = ty * 8 + r;
        int node = n0 + (row >> 2), t = row & 3;
        if (node < N) {
            float* p = g_p1 + ((size_t)node * T + t) * HD;
            *(float4*)(p + 4 * tx)      = make_float4(o[r][0], o[r][1], o[r][2], o[r][3]);
            *(float4*)(p + 64 + 4 * tx) = make_float4(o[r][4], o[r][5], o[r][6], o[r][7]);
        }
    }
    gemm_phase<2, HH, false>(s_h, s_w, w1 + HH * HD, g_zerobias, tid, tx, ty, o);
#pragma unroll
    for (int r = 0; r < 8; r++) {
        int row = ty * 8 + r;
        int node = n0 + (row >> 2), t = row & 3;
        if (node < N) {
            float* p = g_p2 + ((size_t)node * T + t) * HD;
            *(float4*)(p + 4 * tx)      = make_float4(o[r][0], o[r][1], o[r][2], o[r][3]);
            *(float4*)(p + 64 + 4 * tx) = make_float4(o[r][4], o[r][5], o[r][6], o[r][7]);
        }
    }
}

// ---------------- edge kernel: FFMA2 layer-1 + HMMA split-bf16 GEMMs ----------------
__global__ __launch_bounds__(256, 1) void edge_kernel(
    const float* __restrict__ x,
    const int* __restrict__ ei, const float* __restrict__ ea,
    const float* __restrict__ w1, const float* __restrict__ b1,
    const float* __restrict__ b2, const float* __restrict__ cb1,
    const float* __restrict__ cw2, const float* __restrict__ cb2,
    int E)
{
    extern __shared__ __align__(16) char smc[];
    char* sAhi = smc;                 // 128 x 272B = 34816
    char* sAlo = smc + 34816;
    char* sBhi = smc + 69632;
    char* sBlo = smc + 104448;
    float* s_ea   = (float*)(smc + 139264);   // 16 x STRIDE floats
    float* s_w1   = (float*)(smc + 147712);   // 17 x 128 floats
    float* s_bias = (float*)(smc + 156416);   // b2|cb1|cw2

    __shared__ int   s_rown[EPB], s_coln[EPB];
    __shared__ float s_xij[EPB][3][T];
    __shared__ float s_n2[ROWS];

    const int tid = threadIdx.x, tx = tid & 15, ty = tid >> 4;
    const int wid = tid >> 5, t5 = tid & 31;
    const int e0 = blockIdx.x * EPB;

    const u32 sAhi_b = smem_u32(sAhi), sAlo_b = smem_u32(sAlo);
    const u32 sBhi_b = smem_u32(sBhi), sBlo_b = smem_u32(sBlo);

    if (tid < EPB) {
        int eg = e0 + tid; if (eg >= E) eg = E - 1;
        s_rown[tid] = ei[eg];
        s_coln[tid] = ei[E + eg];
    }

    // stage Bhi/Blo = W2 images (row-major 128x256B -> 272B stride)
    {
        int row = tid >> 1, half = tid & 1;
        const float4* sh = (const float4*)((const char*)g_w2hi + row * 256 + half * 128);
        const float4* sl = (const float4*)((const char*)g_w2lo + row * 256 + half * 128);
        float4* dh = (float4*)(sBhi + row * BROW + half * 128);
        float4* dl = (float4*)(sBlo + row * BROW + half * 128);
#pragma unroll
        for (int q = 0; q < 8; q++) { dh[q] = sh[q]; dl[q] = sl[q]; }
    }
    // stage W1 rows 129..144 + row 128
    for (int i = tid; i < 17 * 32; i += 256) {
        int k = i >> 5, cg = i & 31;
        int srcrow = (k == 16) ? 128 : (129 + k);
        *(float4*)(s_w1 + k * HD + cg * 4) = *(const float4*)(w1 + srcrow * HD + cg * 4);
    }
    if (tid < 128) {
        s_bias[tid]       = b2[tid];
        s_bias[128 + tid] = cb1[tid];
        s_bias[256 + tid] = cw2[tid];
    }
    __syncthreads();

    // edge_attr gather
#pragma unroll
    for (int it = 0; it < 2; it++) {
        int idx = it * 256 + tid;
        int k = idx & 15, e = idx >> 4;
        int eg = e0 + e; if (eg >= E) eg = E - 1;
        float4 v = *(const float4*)(ea + ((size_t)eg * HE + k) * T);
        *(float4*)(s_ea + k * STRIDE + e * 4) = v;
    }
    // x_ij, n2
    if (tid < ROWS) {
        int e = tid >> 2, t = tid & 3;
        int rn = s_rown[e], cn = s_coln[e];
        float n2 = 0.f;
#pragma unroll
        for (int d = 0; d < 3; d++) {
            float v = x[((size_t)rn * 3 + d) * T + t] - x[((size_t)cn * 3 + d) * T + t];
            s_xij[e][d][t] = v;
            n2 += v * v;
        }
        s_n2[tid] = n2;
    }
    __syncthreads();

    // ---- layer 1 (FFMA2) ----
    float o1[8][8];
    {
        u64 acc[8][4];
        float4 bA = *(const float4*)(b1 + 4 * tx);
        float4 bB = *(const float4*)(b1 + 64 + 4 * tx);
        float4 wA = *(const float4*)(s_w1 + 16 * HD + 4 * tx);
        float4 wB = *(const float4*)(s_w1 + 16 * HD + 64 + 4 * tx);
#pragma unroll
        for (int r = 0; r < 8; r++) {
            int row = ty * 8 + r;
            int e = row >> 2, t = row & 3;
            const float* p1 = g_p1 + ((size_t)s_rown[e] * T + t) * HD;
            const float* p2 = g_p2 + ((size_t)s_coln[e] * T + t) * HD;
            float4 a1 = *(const float4*)(p1 + 4 * tx);
            float4 c1 = *(const float4*)(p1 + 64 + 4 * tx);
            float4 a2 = *(const float4*)(p2 + 4 * tx);
            float4 c2 = *(const float4*)(p2 + 64 + 4 * tx);
            float n2r = s_n2[row];
            acc[r][0] = packab(bA.x + a1.x + a2.x + n2r * wA.x,
                               bA.y + a1.y + a2.y + n2r * wA.y);
            acc[r][1] = packab(bA.z + a1.z + a2.z + n2r * wA.z,
                               bA.w + a1.w + a2.w + n2r * wA.w);
            acc[r][2] = packab(bB.x + c1.x + c2.x + n2r * wB.x,
                               bB.y + c1.y + c2.y + n2r * wB.y);
            acc[r][3] = packab(bB.z + c1.z + c2.z + n2r * wB.z,
                               bB.w + c1.w + c2.w + n2r * wB.w);
        }
        const float* ap = s_ea + ty * 8;
#pragma unroll
        for (int k = 0; k < HE; k++) {
            float4 a0 = *(const float4*)(ap);
            float4 a1 = *(const float4*)(ap + 4);
            ap += STRIDE;
            ulonglong2 wp0 = *(const ulonglong2*)(s_w1 + k * HD + 4 * tx);
            ulonglong2 wp1 = *(const ulonglong2*)(s_w1 + k * HD + 64 + 4 * tx);
            float av[8] = {a0.x, a0.y, a0.z, a0.w, a1.x, a1.y, a1.z, a1.w};
#pragma unroll
            for (int r = 0; r < 8; r++) {
                u64 ar = pack2(av[r]);
                FMA2(acc[r][0], ar, wp0.x);
                FMA2(acc[r][1], ar, wp0.y);
                FMA2(acc[r][2], ar, wp1.x);
                FMA2(acc[r][3], ar, wp1.y);
            }
        }
#pragma unroll
        for (int r = 0; r < 8; r++)
#pragma unroll
            for (int cp = 0; cp < 4; cp++) {
                float lo, hi; unpack2(acc[r][cp], lo, hi);
                o1[r][2 * cp]     = silu_f(lo);
                o1[r][2 * cp + 1] = silu_f(hi);
            }
    }

    // ---- stage o1 -> sAhi/sAlo (bf16, 272B rows) ----
#pragma unroll
    for (int r = 0; r < 8; r++) {
        int row = ty * 8 + r;
#pragma unroll
        for (int g2 = 0; g2 < 2; g2++) {
            int cb = g2 ? (64 + 4 * tx) : (4 * tx);
            u32 h01, l01, h23, l23;
            split2(o1[r][4 * g2 + 0], o1[r][4 * g2 + 1], h01, l01);
            split2(o1[r][4 * g2 + 2], o1[r][4 * g2 + 3], h23, l23);
            *(uint2*)(sAhi + row * BROW + cb * 2) = make_uint2(h01, h23);
            *(uint2*)(sAlo + row * BROW + cb * 2) = make_uint2(l01, l23);
        }
    }
    __syncthreads();

    // ldmatrix per-thread offsets
    const u32 aoff = (u32)((wid * 16 + (t5 & 15)) * BROW + ((t5 & 16) ? 16 : 0));
    const u32 boff = (u32)(((t5 & 7) + ((t5 >> 4) << 3)) * BROW + ((t5 & 8) << 1));

    float d[16][4];
#pragma unroll
    for (int n = 0; n < 16; n++)
#pragma unroll
        for (int q = 0; q < 4; q++) d[n][q] = 0.f;

    // ---- GEMM1: (Ahi+Alo)@Bhi ----
#pragma unroll 1
    for (int ks = 0; ks < 8; ks++) {
        u32 ah[4], al[4];
        LDMX4(ah[0], ah[1], ah[2], ah[3], sAhi_b + aoff + ks * 32);
        LDMX4(al[0], al[1], al[2], al[3], sAlo_b + aoff + ks * 32);
#pragma unroll
        for (int j = 0; j < 8; j++) {
            u32 b0, b1, b2r, b3;
            LDMX4(b0, b1, b2r, b3, sBhi_b + boff + j * (16 * BROW) + ks * 32);
            MMA16816(d[2 * j],     ah[0], ah[1], ah[2], ah[3], b0, b1);
            MMA16816(d[2 * j + 1], ah[0], ah[1], ah[2], ah[3], b2r, b3);
            MMA16816(d[2 * j],     al[0], al[1], al[2], al[3], b0, b1);
            MMA16816(d[2 * j + 1], al[0], al[1], al[2], al[3], b2r, b3);
        }
    }
    // ---- GEMM1: Ahi@Blo ----
#pragma unroll 1
    for (int ks = 0; ks < 8; ks++) {
        u32 ah[4];
        LDMX4(ah[0], ah[1], ah[2], ah[3], sAhi_b + aoff + ks * 32);
#pragma unroll
        for (int j = 0; j < 8; j++) {
            u32 b0, b1, b2r, b3;
            LDMX4(b0, b1, b2r, b3, sBlo_b + boff + j * (16 * BROW) + ks * 32);
            MMA16816(d[2 * j],     ah[0], ah[1], ah[2], ah[3], b0, b1);
            MMA16816(d[2 * j + 1], ah[0], ah[1], ah[2], ah[3], b2r, b3);
        }
    }

    // ---- readback GEMM1: +b2, silu, scatter m_i, build GEMM2 A-frags ----
    const int g = t5 >> 2, tg = t5 & 3;
    const int rowA = wid * 16 + g, rowB = rowA + 8;
    const int eA = rowA >> 2, tA = rowA & 3;
    const int eB = rowB >> 2, tB = rowB & 3;
    const bool okA = (e0 + eA) < E, okB = (e0 + eB) < E;
    float* mA = g_mi + ((size_t)s_rown[eA] * T + tA) * HD;
    float* mB = g_mi + ((size_t)s_rown[eB] * T + tB) * HD;

    u32 a2h[8][4], a2l[8][4];
#pragma unroll
    for (int n = 0; n < 16; n++) {
        int c = 8 * n + 2 * tg;
        float v0 = silu_f(d[n][0] + s_bias[c]);
        float v1 = silu_f(d[n][1] + s_bias[c + 1]);
        float v2 = silu_f(d[n][2] + s_bias[c]);
        float v3 = silu_f(d[n][3] + s_bias[c + 1]);
        if (okA) REDV2(mA + c, v0, v1);
        if (okB) REDV2(mB + c, v2, v3);
        int ks = n >> 1, p = n & 1;
        split2(v0, v1, a2h[ks][2 * p],     a2l[ks][2 * p]);
        split2(v2, v3, a2h[ks][2 * p + 1], a2l[ks][2 * p + 1]);
    }
    __syncthreads();

    // restage B = CW1 images
    {
        int row = tid >> 1, half = tid & 1;
        const float4* sh = (const float4*)((const char*)g_c1hi + row * 256 + half * 128);
        const float4* sl = (const float4*)((const char*)g_c1lo + row * 256 + half * 128);
        float4* dh = (float4*)(sBhi + row * BROW + half * 128);
        float4* dl = (float4*)(sBlo + row * BROW + half * 128);
#pragma unroll
        for (int q = 0; q < 8; q++) { dh[q] = sh[q]; dl[q] = sl[q]; }
    }
    __syncthreads();

#pragma unroll
    for (int n = 0; n < 16; n++)
#pragma unroll
        for (int q = 0; q < 4; q++) d[n][q] = 0.f;

    // ---- GEMM2: (A2hi+A2lo)@Bhi ----
#pragma unroll 1
    for (int ks = 0; ks < 8; ks++) {
#pragma unroll
        for (int j = 0; j < 8; j++) {
            u32 b0, b1, b2r, b3;
            LDMX4(b0, b1, b2r, b3, sBhi_b + boff + j * (16 * BROW) + ks * 32);
            MMA16816(d[2 * j],     a2h[ks][0], a2h[ks][1], a2h[ks][2], a2h[ks][3], b0, b1);
            MMA16816(d[2 * j + 1], a2h[ks][0], a2h[ks][1], a2h[ks][2], a2h[ks][3], b2r, b3);
            MMA16816(d[2 * j],     a2l[ks][0], a2l[ks][1], a2l[ks][2], a2l[ks][3], b0, b1);
            MMA16816(d[2 * j + 1], a2l[ks][0], a2l[ks][1], a2l[ks][2], a2l[ks][3], b2r, b3);
        }
    }
    // ---- GEMM2: A2hi@Blo ----
#pragma unroll 1
    for (int ks = 0; ks < 8; ks++) {
#pragma unroll
        for (int j = 0; j < 8; j++) {
            u32 b0, b1, b2r, b3;
            LDMX4(b0, b1, b2r, b3, sBlo_b + boff + j * (16 * BROW) + ks * 32);
            MMA16816(d[2 * j],     a2h[ks][0], a2h[ks][1], a2h[ks][2], a2h[ks][3], b0, b1);
            MMA16816(d[2 * j + 1], a2h[ks][0], a2h[ks][1], a2h[ks][2], a2h[ks][3], b2r, b3);
        }
    }

    // ---- readback GEMM2: silu, dot cw2, quad-reduce, coord epilogue ----
    {
        float pA = 0.f, pB = 0.f;
#pragma unroll
        for (int n = 0; n < 16; n++) {
            int c = 8 * n + 2 * tg;
            pA += silu_f(d[n][0] + s_bias[128 + c])     * s_bias[256 + c];
            pA += silu_f(d[n][1] + s_bias[128 + c + 1]) * s_bias[256 + c + 1];
            pB += silu_f(d[n][2] + s_bias[128 + c])     * s_bias[256 + c];
            pB += silu_f(d[n][3] + s_bias[128 + c + 1]) * s_bias[256 + c + 1];
        }
        pA += __shfl_xor_sync(0xffffffffu, pA, 1);
        pA += __shfl_xor_sync(0xffffffffu, pA, 2);
        pB += __shfl_xor_sync(0xffffffffu, pB, 1);
        pB += __shfl_xor_sync(0xffffffffu, pB, 2);
        if (tg == 0) {
            float cb2v = cb2[0];
#pragma unroll
            for (int half = 0; half < 2; half++) {
                int row = half ? rowB : rowA;
                float p = half ? pB : pA;
                int e = row >> 2, t = row & 3;
                if (e0 + e < E) {
                    float cval = (p + cb2v) *
                        __fdividef(1.0f, sqrtf(s_n2[row] + EPSF) + 1.0f);
                    int node = s_rown[e];
#pragma unroll
                    for (int dd = 0; dd < 3; dd++)
                        atomicAdd(&g_agg[((size_t)node * 3 + dd) * T + t],
                                  cval * s_xij[e][dd][t]);
                    if (t == 0) atomicAdd(&g_cnt[node], 1.0f);
                }
            }
        }
    }
}

// ---------------- node kernel ([N,T,HD] g_mi gather) ----------------
__global__ __launch_bounds__(256, 2) void node_kernel(
    const float* __restrict__ x, const float* __restrict__ h,
    const float* __restrict__ nw1, const float* __restrict__ nb1,
    const float* __restrict__ nw2, const float* __restrict__ nb2,
    float* __restrict__ out_x, float* __restrict__ out_h, int N)
{
    extern __shared__ float sm[];
    float* s_buf = sm;
    float* s_w   = sm + HD * STRIDE;

    const int tid = threadIdx.x, tx = tid & 15, ty = tid >> 4;
    const int n0 = blockIdx.x * NPB;

#pragma unroll
    for (int it = 0; it < 2; it++) {
        int idx = it * 256 + tid;
        if (idx < NPB * 12) {
            int n = n0 + idx / 12;
            if (n < N) {
                int rem = idx % 12, d = rem >> 2, t = rem & 3;
                float cv = fmaxf(g_cnt[n], 1.0f);
                int off = (n * 3 + d) * T + t;
                out_x[off] = x[off] + g_agg[off] * __fdividef(1.0f, cv);
            }
        }
    }

    // stage A part 1: ch 0..63 = h; ch 64..127 = m_i k 0..63
#pragma unroll
    for (int it = 0; it < 8; it++) {
        int idx = it * 256 + tid;
        int k = idx & 63, nl = idx >> 6;
        int node = n0 + nl; if (node >= N) node = N - 1;
        float4 v = *(const float4*)(h + ((size_t)node * HH + k) * T);
        *(float4*)(s_buf + k * STRIDE + nl * 4) = v;
    }
#pragma unroll
    for (int it = 0; it < 8; it++) {
        int idx = it * 256 + tid;
        int kq = idx & 15, t = (idx >> 4) & 3, nl = idx >> 6;
        int node = n0 + nl; if (node >= N) node = N - 1;
        float4 v = *(const float4*)(g_mi + ((size_t)node * T + t) * HD + kq * 4);
        s_buf[(HH + kq * 4 + 0) * STRIDE + nl * 4 + t] = v.x;
        s_buf[(HH + kq * 4 + 1) * STRIDE + nl * 4 + t] = v.y;
        s_buf[(HH + kq * 4 + 2) * STRIDE + nl * 4 + t] = v.z;
        s_buf[(HH + kq * 4 + 3) * STRIDE + nl * 4 + t] = v.w;
    }

    u64 acc[8][4];
    {
        float4 bA = *(const float4*)(nb1 + 4 * tx);
        float4 bB = *(const float4*)(nb1 + 64 + 4 * tx);
        u64 i0 = packab(bA.x, bA.y), i1 = packab(bA.z, bA.w);
        u64 i2 = packab(bB.x, bB.y), i3 = packab(bB.z, bB.w);
#pragma unroll
        for (int r = 0; r < 8; r++) {
            acc[r][0] = i0; acc[r][1] = i1; acc[r][2] = i2; acc[r][3] = i3;
        }
    }
    float4 pre[4];
#pragma unroll
    for (int i = 0; i < 4; i++) {
        int off = i * 1024 + tid * 4;
        pre[i] = *(const float4*)(nw1 + (off >> 7) * HD + (off & 127));
    }
#pragma unroll 1
    for (int kc = 0; kc < 4; kc++) {
        __syncthreads();
#pragma unroll
        for (int i = 0; i < 4; i++)
            *(float4*)(s_w + i * 1024 + tid * 4) = pre[i];
        __syncthreads();
        {
            int kbase = (kc + 1) * 32;
            if (kbase < 192) {
#pragma unroll
                for (int i = 0; i < 4; i++) {
                    int off = i * 1024 + tid * 4;
                    pre[i] = *(const float4*)(nw1 + (kbase + (off >> 7)) * HD + (off & 127));
                }
            }
        }
        const float* ap = s_buf + (kc * 32) * STRIDE + ty * 8;
#pragma unroll 8
        for (int kk = 0; kk < 32; kk++) {
            float4 a0 = *(const float4*)(ap);
            float4 a1 = *(const float4*)(ap + 4);
            ap += STRIDE;
            ulonglong2 bA = *(const ulonglong2*)(s_w + kk * HD + 4 * tx);
            ulonglong2 bB = *(const ulonglong2*)(s_w + kk * HD + 64 + 4 * tx);
            float av[8] = {a0.x, a0.y, a0.z, a0.w, a1.x, a1.y, a1.z, a1.w};
#pragma unroll
            for (int r = 0; r < 8; r++) {
                u64 ar = pack2(av[r]);
                FMA2(acc[r][0], ar, bA.x);
                FMA2(acc[r][1], ar, bA.y);
                FMA2(acc[r][2], ar, bB.x);
                FMA2(acc[r][3], ar, bB.y);
            }
        }
    }
    __syncthreads();

    // stage A part 2: m_i k 64..127
#pragma unroll
    for (int it = 0; it < 8; it++) {
        int idx = it * 256 + tid;
        int kq = idx & 15, t = (idx >> 4) & 3, nl = idx >> 6;
        int node = n0 + nl; if (node >= N) node = N - 1;
        float4 v = *(const float4*)(g_mi + ((size_t)node * T + t) * HD + 64 + kq * 4);
        s_buf[(kq * 4 + 0) * STRIDE + nl * 4 + t] = v.x;
        s_buf[(kq * 4 + 1) * STRIDE + nl * 4 + t] = v.y;
        s_buf[(kq * 4 + 2) * STRIDE + nl * 4 + t] = v.z;
        s_buf[(kq * 4 + 3) * STRIDE + nl * 4 + t] = v.w;
    }
#pragma unroll 1
    for (int kc = 0; kc < 2; kc++) {
        __syncthreads();
#pragma unroll
        for (int i = 0; i < 4; i++)
            *(float4*)(s_w + i * 1024 + tid * 4) = pre[i];
        __syncthreads();
        if (kc == 0) {
#pragma unroll
            for (int i = 0; i < 4; i++) {
                int off = i * 1024 + tid * 4;
                pre[i] = *(const float4*)(nw1 + (160 + (off >> 7)) * HD + (off & 127));
            }
        }
        const float* ap = s_buf + (kc * 32) * STRIDE + ty * 8;
#pragma unroll 8
        for (int kk = 0; kk < 32; kk++) {
            float4 a0 = *(const float4*)(ap);
            float4 a1 = *(const float4*)(ap + 4);
            ap += STRIDE;
            ulonglong2 bA = *(const ulonglong2*)(s_w + kk * HD + 4 * tx);
            ulonglong2 bB = *(const ulonglong2*)(s_w + kk * HD + 64 + 4 * tx);
            float av[8] = {a0.x, a0.y, a0.z, a0.w, a1.x, a1.y, a1.z, a1.w};
#pragma unroll
            for (int r = 0; r < 8; r++) {
                u64 ar = pack2(av[r]);
                FMA2(acc[r][0], ar, bA.x);
                FMA2(acc[r][1], ar, bA.y);
                FMA2(acc[r][2], ar, bB.x);
                FMA2(acc[r][3], ar, bB.y);
            }
        }
    }

    float o1[8][8];
#pragma unroll
    for (int r = 0; r < 8; r++)
#pragma unroll
        for (int cp = 0; cp < 4; cp++) {
            float lo, hi; unpack2(acc[r][cp], lo, hi);
            o1[r][2 * cp]     = silu_f(lo);
            o1[r][2 * cp + 1] = silu_f(hi);
        }
    __syncthreads();
#pragma unroll
    for (int c = 0; c < 8; c++) {
        int col = (c < 4) ? 4 * tx + c : 60 + 4 * tx + c;
        *(float4*)(s_buf + col * STRIDE + ty * 8) =
            make_float4(o1[0][c], o1[1][c], o1[2][c], o1[3][c]);
        *(float4*)(s_buf + col * STRIDE + ty * 8 + 4) =
            make_float4(o1[4][c], o1[5][c], o1[6][c], o1[7][c]);
    }

    u64 acc2[8][2];
    {
        float4 b = *(const float4*)(nb2 + 4 * tx);
        u64 i0 = packab(b.x, b.y), i1 = packab(b.z, b.w);
#pragma unroll
        for (int r = 0; r < 8; r++) { acc2[r][0] = i0; acc2[r][1] = i1; }
    }
    float4 pre2[2];
#pragma unroll
    for (int i = 0; i < 2; i++) {
        int off = i * 1024 + tid * 4;
        pre2[i] = *(const float4*)(nw2 + (off >> 6) * HH + (off & 63));
    }
#pragma unroll 1
    for (int kc = 0; kc < 4; kc++) {
        __syncthreads();
#pragma unroll
        for (int i = 0; i < 2; i++)
            *(float4*)(s_w + i * 1024 + tid * 4) = pre2[i];
        __syncthreads();
        if (kc < 3) {
#pragma unroll
            for (int i = 0; i < 2; i++) {
                int off = i * 1024 + tid * 4;
                pre2[i] = *(const float4*)(nw2 + ((kc + 1) * 32 + (off >> 6)) * HH + (off & 63));
            }
        }
        const float* ap = s_buf + (kc * 32) * STRIDE + ty * 8;
#pragma unroll 8
        for (int kk = 0; kk < 32; kk++) {
            float4 a0 = *(const float4*)(ap);
            float4 a1 = *(const float4*)(ap + 4);
            ap += STRIDE;
            ulonglong2 w01 = *(const ulonglong2*)(s_w + kk * HH + 4 * tx);
            float av[8] = {a0.x, a0.y, a0.z, a0.w, a1.x, a1.y, a1.z, a1.w};
#pragma unroll
            for (int r = 0; r < 8; r++) {
                u64 ar = pack2(av[r]);
                FMA2(acc2[r][0], ar, w01.x);
                FMA2(acc2[r][1], ar, w01.y);
            }
        }
    }
    float o2[8][4];
#pragma unroll
    for (int r = 0; r < 8; r++) {
        unpack2(acc2[r][0], o2[r][0], o2[r][1]);
        unpack2(acc2[r][1], o2[r][2], o2[r][3]);
    }
#pragma unroll
    for (int half = 0; half < 2; half++) {
        int n = n0 + 2 * ty + half;
        if (n < N) {
#pragma unroll
            for (int c = 0; c < 4; c++) {
                int col = 4 * tx + c;
                *(float4*)(out_h + ((size_t)n * HH + col) * T) =
                    make_float4(o2[half * 4 + 0][c], o2[half * 4 + 1][c],
                                o2[half * 4 + 2][c], o2[half * 4 + 3][c]);
            }
        }
    }
}

extern "C" void kernel_launch(void* const* d_in, const int* in_sizes, int n_in,
                              void* d_out, int out_size)
{
    const float* x   = (const float*)d_in[0];
    const float* h   = (const float*)d_in[1];
    const int*   ei  = (const int*)  d_in[2];
    const float* ea  = (const float*)d_in[3];
    const float* ew1 = (const float*)d_in[5];
    const float* eb1 = (const float*)d_in[6];
    const float* ew2 = (const float*)d_in[7];
    const float* eb2 = (const float*)d_in[8];
    const float* cw1 = (const float*)d_in[9];
    const float* cb1 = (const float*)d_in[10];
    const float* cw2 = (const float*)d_in[11];
    const float* cb2 = (const float*)d_in[12];
    const float* nw1 = (const float*)d_in[13];
    const float* nb1 = (const float*)d_in[14];
    const float* nw2 = (const float*)d_in[15];
    const float* nb2 = (const float*)d_in[16];

    int N = in_sizes[0] / (3 * T);
    int E = in_sizes[3] / (HE * T);

    float* out_x = (float*)d_out;
    float* out_h = out_x + (size_t)N * 3 * T;

    const int pre_smem  = (HH * STRIDE + 32 * HD) * sizeof(float);
    const int node_smem = (HD * STRIDE + 32 * HD) * sizeof(float);
    const int edge_smem = 157952;
    cudaFuncSetAttribute(pre_kernel,  cudaFuncAttributeMaxDynamicSharedMemorySize, pre_smem);
    cudaFuncSetAttribute(node_kernel, cudaFuncAttributeMaxDynamicSharedMemorySize, node_smem);
    cudaFuncSetAttribute(edge_kernel, cudaFuncAttributeMaxDynamicSharedMemorySize, edge_smem);

    zero_kernel<<<2048, 256>>>(N);
    wimg_kernel<<<(HD * HD) / 256, 256>>>(ew2, cw1);
    pre_kernel<<<(N + NPRE - 1) / NPRE, 256, pre_smem>>>(h, ew1, N);
    edge_kernel<<<(E + EPB - 1) / EPB, 256, edge_smem>>>(
        x, ei, ea, ew1, eb1, eb2, cb1, cw2, cb2, E);
    node_kernel<<<(N + NPB - 1) / NPB, 256, node_smem>>>(
        x, h, nw1, nb1, nw2, nb2, out_x, out_h, N);
}

// round 13
// speedup vs baseline: 4.3915x; 1.0001x over previous
#include <cuda_runtime.h>
#include <cuda_bf16.h>
#include <cstdint>

#define T    4
#define HH   64
#define HE   16
#define HD   128
#define EPB  32
#define ROWS 128
#define STRIDE 132
#define NPRE 32
#define NPB  32
#define MAXN 20000
#define EPSF 1e-8f
#define BROW 272          // bf16 operand row stride in bytes (136 bf16)

typedef unsigned long long u64;
typedef unsigned int u32;

// ---------------- device globals ----------------
__device__ float g_mi[MAXN * T * HD];          // [N, T, HD]
__device__ float g_agg[MAXN * 3 * T];
__device__ float g_cnt[MAXN];
__device__ float g_p1[(size_t)MAXN * T * HD];
__device__ float g_p2[(size_t)MAXN * T * HD];
__device__ float g_zerobias[HD];
// plain [n][k] bf16 hi/lo images of W2^T and CW1^T
__device__ __nv_bfloat16 g_w2hi[HD * HD], g_w2lo[HD * HD];
__device__ __nv_bfloat16 g_c1hi[HD * HD], g_c1lo[HD * HD];

__device__ __forceinline__ float silu_f(float v) {
    return v * __fdividef(1.0f, 1.0f + __expf(-v));
}

#define FMA2(d, a, b) asm("fma.rn.f32x2 %0, %1, %2, %0;" : "+l"(d) : "l"(a), "l"(b))
__device__ __forceinline__ u64 packab(float a, float b) {
    u64 r; asm("mov.b64 %0, {%1, %2};" : "=l"(r) : "f"(a), "f"(b)); return r;
}
__device__ __forceinline__ u64 pack2(float v) { return packab(v, v); }
__device__ __forceinline__ void unpack2(u64 v, float& lo, float& hi) {
    asm("mov.b64 {%0, %1}, %2;" : "=f"(lo), "=f"(hi) : "l"(v));
}
__device__ __forceinline__ u32 smem_u32(const void* p) {
    u32 a;
    asm("{ .reg .u64 t; cvta.to.shared.u64 t, %1; cvt.u32.u64 %0, t; }"
        : "=r"(a) : "l"(p));
    return a;
}
// bf16 pair hi/lo split
__device__ __forceinline__ void split2(float a, float b, u32& h, u32& l) {
    __nv_bfloat162 hp, lp;
    hp.x = __float2bfloat16(a); hp.y = __float2bfloat16(b);
    lp.x = __float2bfloat16(a - __bfloat162float(hp.x));
    lp.y = __float2bfloat16(b - __bfloat162float(hp.y));
    h = *reinterpret_cast<u32*>(&hp);
    l = *reinterpret_cast<u32*>(&lp);
}

#define LDMX4(r0, r1, r2, r3, addr) \
    asm volatile("ldmatrix.sync.aligned.m8n8.x4.shared.b16 {%0,%1,%2,%3}, [%4];" \
        : "=r"(r0), "=r"(r1), "=r"(r2), "=r"(r3) : "r"(addr))

#define MMA16816(d, a0, a1, a2, a3, b0, b1) \
    asm volatile("mma.sync.aligned.m16n8k16.row.col.f32.bf16.bf16.f32 " \
        "{%0,%1,%2,%3}, {%4,%5,%6,%7}, {%8,%9}, {%0,%1,%2,%3};" \
        : "+f"((d)[0]), "+f"((d)[1]), "+f"((d)[2]), "+f"((d)[3]) \
        : "r"(a0), "r"(a1), "r"(a2), "r"(a3), "r"(b0), "r"(b1))

#define REDV2(p, v0, v1) \
    asm volatile("red.global.add.v2.f32 [%0], {%1,%2};" \
                 :: "l"(p), "f"(v0), "f"(v1) : "memory")

// ---------------- small kernels ----------------
__global__ void zero_kernel(int n) {
    int stride = gridDim.x * blockDim.x;
    int base = blockIdx.x * blockDim.x + threadIdx.x;
    for (int i = base; i < n * HD * T; i += stride) g_mi[i] = 0.0f;
    for (int i = base; i < n * 3 * T;  i += stride) g_agg[i] = 0.0f;
    for (int i = base; i < n;          i += stride) g_cnt[i] = 0.0f;
}

// plain [n][k] bf16 hi/lo weight images (B^T: img[n*128+k] = W[k][n])
__global__ void wimg_kernel(const float* __restrict__ w2, const float* __restrict__ cw1) {
    int idx = blockIdx.x * 256 + threadIdx.x;   // 16384
    int n = idx >> 7, k = idx & 127;
    float v2 = w2[k * HD + n];
    __nv_bfloat16 h2 = __float2bfloat16(v2);
    g_w2hi[idx] = h2;
    g_w2lo[idx] = __float2bfloat16(v2 - __bfloat162float(h2));
    float v3 = cw1[k * HD + n];
    __nv_bfloat16 h3 = __float2bfloat16(v3);
    g_c1hi[idx] = h3;
    g_c1lo[idx] = __float2bfloat16(v3 - __bfloat162float(h3));
}

// ---------------- FFMA2 GEMM tile (pre/node kernels) ----------------
template<int NCHUNK, int KLIM, bool ACT>
__device__ __forceinline__ void gemm_phase(
    const float* __restrict__ sA, float* __restrict__ sW,
    const float* __restrict__ gW, const float* __restrict__ gB,
    int tid, int tx, int ty, float (&out)[8][8])
{
    u64 acc[8][4];
    {
        float4 bA = *(const float4*)(gB + 4 * tx);
        float4 bB = *(const float4*)(gB + 64 + 4 * tx);
        u64 i0 = packab(bA.x, bA.y), i1 = packab(bA.z, bA.w);
        u64 i2 = packab(bB.x, bB.y), i3 = packab(bB.z, bB.w);
#pragma unroll
        for (int r = 0; r < 8; r++) {
            acc[r][0] = i0; acc[r][1] = i1; acc[r][2] = i2; acc[r][3] = i3;
        }
    }
    float4 pre[4];
#pragma unroll
    for (int i = 0; i < 4; i++) {
        int off = i * 1024 + tid * 4;
        int kg = off >> 7;
        pre[i] = (kg < KLIM) ? *(const float4*)(gW + kg * HD + (off & 127))
                             : make_float4(0.f, 0.f, 0.f, 0.f);
    }
#pragma unroll 1
    for (int kc = 0; kc < NCHUNK; kc++) {
        __syncthreads();
#pragma unroll
        for (int i = 0; i < 4; i++)
            *(float4*)(sW + i * 1024 + tid * 4) = pre[i];
        __syncthreads();
        if (kc + 1 < NCHUNK) {
#pragma unroll
            for (int i = 0; i < 4; i++) {
                int off = i * 1024 + tid * 4;
                int kg = (kc + 1) * 32 + (off >> 7);
                pre[i] = (kg < KLIM) ? *(const float4*)(gW + kg * HD + (off & 127))
                                     : make_float4(0.f, 0.f, 0.f, 0.f);
            }
        }
        const float* ap = sA + (kc * 32) * STRIDE + ty * 8;
#pragma unroll 8
        for (int kk = 0; kk < 32; kk++) {
            float4 a0 = *(const float4*)(ap);
            float4 a1 = *(const float4*)(ap + 4);
            ap += STRIDE;
            ulonglong2 bA = *(const ulonglong2*)(sW + kk * HD + 4 * tx);
            ulonglong2 bB = *(const ulonglong2*)(sW + kk * HD + 64 + 4 * tx);
            float av[8] = {a0.x, a0.y, a0.z, a0.w, a1.x, a1.y, a1.z, a1.w};
#pragma unroll
            for (int r = 0; r < 8; r++) {
                u64 ar = pack2(av[r]);
                FMA2(acc[r][0], ar, bA.x);
                FMA2(acc[r][1], ar, bA.y);
                FMA2(acc[r][2], ar, bB.x);
                FMA2(acc[r][3], ar, bB.y);
            }
        }
    }
#pragma unroll
    for (int r = 0; r < 8; r++)
#pragma unroll
        for (int cp = 0; cp < 4; cp++) {
            float lo, hi; unpack2(acc[r][cp], lo, hi);
            out[r][cp * 2]     = ACT ? silu_f(lo) : lo;
            out[r][cp * 2 + 1] = ACT ? silu_f(hi) : hi;
        }
}

// ---------------- P1/P2 precompute ----------------
__global__ __launch_bounds__(256, 2) void pre_kernel(
    const float* __restrict__ h, const float* __restrict__ w1, int N)
{
    extern __shared__ float sm[];
    float* s_h = sm;
    float* s_w = sm + HH * STRIDE;
    const int tid = threadIdx.x, tx = tid & 15, ty = tid >> 4;
    const int n0 = blockIdx.x * NPRE;
#pragma unroll
    for (int it = 0; it < 8; it++) {
        int idx = it * 256 + tid;
        int k = idx & 63, nl = idx >> 6;
        int node = n0 + nl; if (node >= N) node = N - 1;
        float4 v = *(const float4*)(h + ((size_t)node * HH + k) * T);
        *(float4*)(s_h + k * STRIDE + nl * 4) = v;
    }
    float o[8][8];
    gemm_phase<2, HH, false>(s_h, s_w, w1, g_zerobias, tid, tx, ty, o);
#pragma unroll
    for (int r = 0; r < 8; r++) {
        int row = ty * 8 + r;
        int node = n0 + (row >> 2), t = row & 3;
        if (node < N) {
            float* p = g_p1 + ((size_t)node * T + t) * HD;
            *(float4*)(p + 4 * tx)      = make_float4(o[r][0], o[r][1], o[r][2], o[r][3]);
            *(float4*)(p + 64 + 4 * tx) = make_float4(o[r][4], o[r][5], o[r][6], o[r][7]);
        }
    }
    gemm_phase<2, HH, false>(s_h, s_w, w1 + HH * HD, g_zerobias, tid, tx, ty, o);
#pragma unroll
    for (int r = 0; r < 8; r++) {
        int row = ty * 8 + r;
        int node = n0 + (row >> 2), t = row & 3;
        if (node < N) {
            float* p = g_p2 + ((size_t)node * T + t) * HD;
            *(float4*)(p + 4 * tx)      = make_float4(o[r][0], o[r][1], o[r][2], o[r][3]);
            *(float4*)(p + 64 + 4 * tx) = make_float4(o[r][4], o[r][5], o[r][6], o[r][7]);
        }
    }
}

// ---------------- edge kernel: FFMA2 layer-1 + HMMA split-bf16 GEMMs ----------------
__global__ __launch_bounds__(256, 1) void edge_kernel(
    const float* __restrict__ x,
    const int* __restrict__ ei, const float* __restrict__ ea,
    const float* __restrict__ w1, const float* __restrict__ b1,
    const float* __restrict__ b2, const float* __restrict__ cb1,
    const float* __restrict__ cw2, const float* __restrict__ cb2,
    int E)
{
    extern __shared__ __align__(16) char smc[];
    char* sAhi = smc;                 // 128 x 272B = 34816
    char* sAlo = smc + 34816;
    char* sBhi = smc + 69632;
    char* sBlo = smc + 104448;
    float* s_ea   = (float*)(smc + 139264);   // 16 x STRIDE floats
    float* s_w1   = (float*)(smc + 147712);   // 17 x 128 floats
    float* s_bias = (float*)(smc + 156416);   // b2|cb1|cw2

    __shared__ int   s_rown[EPB], s_coln[EPB];
    __shared__ float s_xij[EPB][3][T];
    __shared__ float s_n2[ROWS];

    const int tid = threadIdx.x, tx = tid & 15, ty = tid >> 4;
    const int wid = tid >> 5, t5 = tid & 31;
    const int e0 = blockIdx.x * EPB;

    const u32 sAhi_b = smem_u32(sAhi), sAlo_b = smem_u32(sAlo);
    const u32 sBhi_b = smem_u32(sBhi), sBlo_b = smem_u32(sBlo);

    if (tid < EPB) {
        int eg = e0 + tid; if (eg >= E) eg = E - 1;
        s_rown[tid] = ei[eg];
        s_coln[tid] = ei[E + eg];
    }

    // stage Bhi/Blo = W2 images (row-major 128x256B -> 272B stride)
    {
        int row = tid >> 1, half = tid & 1;
        const float4* sh = (const float4*)((const char*)g_w2hi + row * 256 + half * 128);
        const float4* sl = (const float4*)((const char*)g_w2lo + row * 256 + half * 128);
        float4* dh = (float4*)(sBhi + row * BROW + half * 128);
        float4* dl = (float4*)(sBlo + row * BROW + half * 128);
#pragma unroll
        for (int q = 0; q < 8; q++) { dh[q] = sh[q]; dl[q] = sl[q]; }
    }
    // stage W1 rows 129..144 + row 128
    for (int i = tid; i < 17 * 32; i += 256) {
        int k = i >> 5, cg = i & 31;
        int srcrow = (k == 16) ? 128 : (129 + k);
        *(float4*)(s_w1 + k * HD + cg * 4) = *(const float4*)(w1 + srcrow * HD + cg * 4);
    }
    if (tid < 128) {
        s_bias[tid]       = b2[tid];
        s_bias[128 + tid] = cb1[tid];
        s_bias[256 + tid] = cw2[tid];
    }
    __syncthreads();

    // edge_attr gather
#pragma unroll
    for (int it = 0; it < 2; it++) {
        int idx = it * 256 + tid;
        int k = idx & 15, e = idx >> 4;
        int eg = e0 + e; if (eg >= E) eg = E - 1;
        float4 v = *(const float4*)(ea + ((size_t)eg * HE + k) * T);
        *(float4*)(s_ea + k * STRIDE + e * 4) = v;
    }
    // x_ij, n2
    if (tid < ROWS) {
        int e = tid >> 2, t = tid & 3;
        int rn = s_rown[e], cn = s_coln[e];
        float n2 = 0.f;
#pragma unroll
        for (int d = 0; d < 3; d++) {
            float v = x[((size_t)rn * 3 + d) * T + t] - x[((size_t)cn * 3 + d) * T + t];
            s_xij[e][d][t] = v;
            n2 += v * v;
        }
        s_n2[tid] = n2;
    }
    __syncthreads();

    // ---- layer 1 (FFMA2) ----
    float o1[8][8];
    {
        u64 acc[8][4];
        float4 bA = *(const float4*)(b1 + 4 * tx);
        float4 bB = *(const float4*)(b1 + 64 + 4 * tx);
        float4 wA = *(const float4*)(s_w1 + 16 * HD + 4 * tx);
        float4 wB = *(const float4*)(s_w1 + 16 * HD + 64 + 4 * tx);
#pragma unroll
        for (int r = 0; r < 8; r++) {
            int row = ty * 8 + r;
            int e = row >> 2, t = row & 3;
            const float* p1 = g_p1 + ((size_t)s_rown[e] * T + t) * HD;
            const float* p2 = g_p2 + ((size_t)s_coln[e] * T + t) * HD;
            float4 a1 = *(const float4*)(p1 + 4 * tx);
            float4 c1 = *(const float4*)(p1 + 64 + 4 * tx);
            float4 a2 = *(const float4*)(p2 + 4 * tx);
            float4 c2 = *(const float4*)(p2 + 64 + 4 * tx);
            float n2r = s_n2[row];
            acc[r][0] = packab(bA.x + a1.x + a2.x + n2r * wA.x,
                               bA.y + a1.y + a2.y + n2r * wA.y);
            acc[r][1] = packab(bA.z + a1.z + a2.z + n2r * wA.z,
                               bA.w + a1.w + a2.w + n2r * wA.w);
            acc[r][2] = packab(bB.x + c1.x + c2.x + n2r * wB.x,
                               bB.y + c1.y + c2.y + n2r * wB.y);
            acc[r][3] = packab(bB.z + c1.z + c2.z + n2r * wB.z,
                               bB.w + c1.w + c2.w + n2r * wB.w);
        }
        const float* ap = s_ea + ty * 8;
#pragma unroll
        for (int k = 0; k < HE; k++) {
            float4 a0 = *(const float4*)(ap);
            float4 a1 = *(const float4*)(ap + 4);
            ap += STRIDE;
            ulonglong2 wp0 = *(const ulonglong2*)(s_w1 + k * HD + 4 * tx);
            ulonglong2 wp1 = *(const ulonglong2*)(s_w1 + k * HD + 64 + 4 * tx);
            float av[8] = {a0.x, a0.y, a0.z, a0.w, a1.x, a1.y, a1.z, a1.w};
#pragma unroll
            for (int r = 0; r < 8; r++) {
                u64 ar = pack2(av[r]);
                FMA2(acc[r][0], ar, wp0.x);
                FMA2(acc[r][1], ar, wp0.y);
                FMA2(acc[r][2], ar, wp1.x);
                FMA2(acc[r][3], ar, wp1.y);
            }
        }
#pragma unroll
        for (int r = 0; r < 8; r++)
#pragma unroll
            for (int cp = 0; cp < 4; cp++) {
                float lo, hi; unpack2(acc[r][cp], lo, hi);
                o1[r][2 * cp]     = silu_f(lo);
                o1[r][2 * cp + 1] = silu_f(hi);
            }
    }

    // ---- stage o1 -> sAhi/sAlo (bf16, 272B rows) ----
#pragma unroll
    for (int r = 0; r < 8; r++) {
        int row = ty * 8 + r;
#pragma unroll
        for (int g2 = 0; g2 < 2; g2++) {
            int cb = g2 ? (64 + 4 * tx) : (4 * tx);
            u32 h01, l01, h23, l23;
            split2(o1[r][4 * g2 + 0], o1[r][4 * g2 + 1], h01, l01);
            split2(o1[r][4 * g2 + 2], o1[r][4 * g2 + 3], h23, l23);
            *(uint2*)(sAhi + row * BROW + cb * 2) = make_uint2(h01, h23);
            *(uint2*)(sAlo + row * BROW + cb * 2) = make_uint2(l01, l23);
        }
    }
    __syncthreads();

    // ldmatrix per-thread offsets
    const u32 aoff = (u32)((wid * 16 + (t5 & 15)) * BROW + ((t5 & 16) ? 16 : 0));
    const u32 boff = (u32)(((t5 & 7) + ((t5 >> 4) << 3)) * BROW + ((t5 & 8) << 1));

    float d[16][4];
#pragma unroll
    for (int n = 0; n < 16; n++)
#pragma unroll
        for (int q = 0; q < 4; q++) d[n][q] = 0.f;

    // ---- GEMM1: (Ahi+Alo)@Bhi ----
#pragma unroll 1
    for (int ks = 0; ks < 8; ks++) {
        u32 ah[4], al[4];
        LDMX4(ah[0], ah[1], ah[2], ah[3], sAhi_b + aoff + ks * 32);
        LDMX4(al[0], al[1], al[2], al[3], sAlo_b + aoff + ks * 32);
#pragma unroll
        for (int j = 0; j < 8; j++) {
            u32 b0, b1, b2r, b3;
            LDMX4(b0, b1, b2r, b3, sBhi_b + boff + j * (16 * BROW) + ks * 32);
            MMA16816(d[2 * j],     ah[0], ah[1], ah[2], ah[3], b0, b1);
            MMA16816(d[2 * j + 1], ah[0], ah[1], ah[2], ah[3], b2r, b3);
            MMA16816(d[2 * j],     al[0], al[1], al[2], al[3], b0, b1);
            MMA16816(d[2 * j + 1], al[0], al[1], al[2], al[3], b2r, b3);
        }
    }
    // ---- GEMM1: Ahi@Blo ----
#pragma unroll 1
    for (int ks = 0; ks < 8; ks++) {
        u32 ah[4];
        LDMX4(ah[0], ah[1], ah[2], ah[3], sAhi_b + aoff + ks * 32);
#pragma unroll
        for (int j = 0; j < 8; j++) {
            u32 b0, b1, b2r, b3;
            LDMX4(b0, b1, b2r, b3, sBlo_b + boff + j * (16 * BROW) + ks * 32);
            MMA16816(d[2 * j],     ah[0], ah[1], ah[2], ah[3], b0, b1);
            MMA16816(d[2 * j + 1], ah[0], ah[1], ah[2], ah[3], b2r, b3);
        }
    }

    // ---- readback GEMM1: +b2, silu, scatter m_i, build GEMM2 A-frags ----
    const int g = t5 >> 2, tg = t5 & 3;
    const int rowA = wid * 16 + g, rowB = rowA + 8;
    const int eA = rowA >> 2, tA = rowA & 3;
    const int eB = rowB >> 2, tB = rowB & 3;
    const bool okA = (e0 + eA) < E, okB = (e0 + eB) < E;
    float* mA = g_mi + ((size_t)s_rown[eA] * T + tA) * HD;
    float* mB = g_mi + ((size_t)s_rown[eB] * T + tB) * HD;

    u32 a2h[8][4], a2l[8][4];
#pragma unroll
    for (int n = 0; n < 16; n++) {
        int c = 8 * n + 2 * tg;
        float v0 = silu_f(d[n][0] + s_bias[c]);
        float v1 = silu_f(d[n][1] + s_bias[c + 1]);
        float v2 = silu_f(d[n][2] + s_bias[c]);
        float v3 = silu_f(d[n][3] + s_bias[c + 1]);
        if (okA) REDV2(mA + c, v0, v1);
        if (okB) REDV2(mB + c, v2, v3);
        int ks = n >> 1, p = n & 1;
        split2(v0, v1, a2h[ks][2 * p],     a2l[ks][2 * p]);
        split2(v2, v3, a2h[ks][2 * p + 1], a2l[ks][2 * p + 1]);
    }
    __syncthreads();

    // restage B = CW1 images
    {
        int row = tid >> 1, half = tid & 1;
        const float4* sh = (const float4*)((const char*)g_c1hi + row * 256 + half * 128);
        const float4* sl = (const float4*)((const char*)g_c1lo + row * 256 + half * 128);
        float4* dh = (float4*)(sBhi + row * BROW + half * 128);
        float4* dl = (float4*)(sBlo + row * BROW + half * 128);
#pragma unroll
        for (int q = 0; q < 8; q++) { dh[q] = sh[q]; dl[q] = sl[q]; }
    }
    __syncthreads();

#pragma unroll
    for (int n = 0; n < 16; n++)
#pragma unroll
        for (int q = 0; q < 4; q++) d[n][q] = 0.f;

    // ---- GEMM2: (A2hi+A2lo)@Bhi ----
#pragma unroll 1
    for (int ks = 0; ks < 8; ks++) {
#pragma unroll
        for (int j = 0; j < 8; j++) {
            u32 b0, b1, b2r, b3;
            LDMX4(b0, b1, b2r, b3, sBhi_b + boff + j * (16 * BROW) + ks * 32);
            MMA16816(d[2 * j],     a2h[ks][0], a2h[ks][1], a2h[ks][2], a2h[ks][3], b0, b1);
            MMA16816(d[2 * j + 1], a2h[ks][0], a2h[ks][1], a2h[ks][2], a2h[ks][3], b2r, b3);
            MMA16816(d[2 * j],     a2l[ks][0], a2l[ks][1], a2l[ks][2], a2l[ks][3], b0, b1);
            MMA16816(d[2 * j + 1], a2l[ks][0], a2l[ks][1], a2l[ks][2], a2l[ks][3], b2r, b3);
        }
    }
    // ---- GEMM2: A2hi@Blo ----
#pragma unroll 1
    for (int ks = 0; ks < 8; ks++) {
#pragma unroll
        for (int j = 0; j < 8; j++) {
            u32 b0, b1, b2r, b3;
            LDMX4(b0, b1, b2r, b3, sBlo_b + boff + j * (16 * BROW) + ks * 32);
            MMA16816(d[2 * j],     a2h[ks][0], a2h[ks][1], a2h[ks][2], a2h[ks][3], b0, b1);
            MMA16816(d[2 * j + 1], a2h[ks][0], a2h[ks][1], a2h[ks][2], a2h[ks][3], b2r, b3);
        }
    }

    // ---- readback GEMM2: silu, dot cw2, quad-reduce, coord epilogue ----
    {
        float pA = 0.f, pB = 0.f;
#pragma unroll
        for (int n = 0; n < 16; n++) {
            int c = 8 * n + 2 * tg;
            pA += silu_f(d[n][0] + s_bias[128 + c])     * s_bias[256 + c];
            pA += silu_f(d[n][1] + s_bias[128 + c + 1]) * s_bias[256 + c + 1];
            pB += silu_f(d[n][2] + s_bias[128 + c])     * s_bias[256 + c];
            pB += silu_f(d[n][3] + s_bias[128 + c + 1]) * s_bias[256 + c + 1];
        }
        pA += __shfl_xor_sync(0xffffffffu, pA, 1);
        pA += __shfl_xor_sync(0xffffffffu, pA, 2);
        pB += __shfl_xor_sync(0xffffffffu, pB, 1);
        pB += __shfl_xor_sync(0xffffffffu, pB, 2);
        if (tg == 0) {
            float cb2v = cb2[0];
#pragma unroll
            for (int half = 0; half < 2; half++) {
                int row = half ? rowB : rowA;
                float p = half ? pB : pA;
                int e = row >> 2, t = row & 3;
                if (e0 + e < E) {
                    float cval = (p + cb2v) *
                        __fdividef(1.0f, sqrtf(s_n2[row] + EPSF) + 1.0f);
                    int node = s_rown[e];
#pragma unroll
                    for (int dd = 0; dd < 3; dd++)
                        atomicAdd(&g_agg[((size_t)node * 3 + dd) * T + t],
                                  cval * s_xij[e][dd][t]);
                    if (t == 0) atomicAdd(&g_cnt[node], 1.0f);
                }
            }
        }
    }
}

// ---------------- node kernel ([N,T,HD] g_mi gather) ----------------
__global__ __launch_bounds__(256, 2) void node_kernel(
    const float* __restrict__ x, const float* __restrict__ h,
    const float* __restrict__ nw1, const float* __restrict__ nb1,
    const float* __restrict__ nw2, const float* __restrict__ nb2,
    float* __restrict__ out_x, float* __restrict__ out_h, int N)
{
    extern __shared__ float sm[];
    float* s_buf = sm;
    float* s_w   = sm + HD * STRIDE;

    const int tid = threadIdx.x, tx = tid & 15, ty = tid >> 4;
    const int n0 = blockIdx.x * NPB;

#pragma unroll
    for (int it = 0; it < 2; it++) {
        int idx = it * 256 + tid;
        if (idx < NPB * 12) {
            int n = n0 + idx / 12;
            if (n < N) {
                int rem = idx % 12, d = rem >> 2, t = rem & 3;
                float cv = fmaxf(g_cnt[n], 1.0f);
                int off = (n * 3 + d) * T + t;
                out_x[off] = x[off] + g_agg[off] * __fdividef(1.0f, cv);
            }
        }
    }

    // stage A part 1: ch 0..63 = h; ch 64..127 = m_i k 0..63
#pragma unroll
    for (int it = 0; it < 8; it++) {
        int idx = it * 256 + tid;
        int k = idx & 63, nl = idx >> 6;
        int node = n0 + nl; if (node >= N) node = N - 1;
        float4 v = *(const float4*)(h + ((size_t)node * HH + k) * T);
        *(float4*)(s_buf + k * STRIDE + nl * 4) = v;
    }
#pragma unroll
    for (int it = 0; it < 8; it++) {
        int idx = it * 256 + tid;
        int kq = idx & 15, t = (idx >> 4) & 3, nl = idx >> 6;
        int node = n0 + nl; if (node >= N) node = N - 1;
        float4 v = *(const float4*)(g_mi + ((size_t)node * T + t) * HD + kq * 4);
        s_buf[(HH + kq * 4 + 0) * STRIDE + nl * 4 + t] = v.x;
        s_buf[(HH + kq * 4 + 1) * STRIDE + nl * 4 + t] = v.y;
        s_buf[(HH + kq * 4 + 2) * STRIDE + nl * 4 + t] = v.z;
        s_buf[(HH + kq * 4 + 3) * STRIDE + nl * 4 + t] = v.w;
    }

    u64 acc[8][4];
    {
        float4 bA = *(const float4*)(nb1 + 4 * tx);
        float4 bB = *(const float4*)(nb1 + 64 + 4 * tx);
        u64 i0 = packab(bA.x, bA.y), i1 = packab(bA.z, bA.w);
        u64 i2 = packab(bB.x, bB.y), i3 = packab(bB.z, bB.w);
#pragma unroll
        for (int r = 0; r < 8; r++) {
            acc[r][0] = i0; acc[r][1] = i1; acc[r][2] = i2; acc[r][3] = i3;
        }
    }
    float4 pre[4];
#pragma unroll
    for (int i = 0; i < 4; i++) {
        int off = i * 1024 + tid * 4;
        pre[i] = *(const float4*)(nw1 + (off >> 7) * HD + (off & 127));
    }
#pragma unroll 1
    for (int kc = 0; kc < 4; kc++) {
        __syncthreads();
#pragma unroll
        for (int i = 0; i < 4; i++)
            *(float4*)(s_w + i * 1024 + tid * 4) = pre[i];
        __syncthreads();
        {
            int kbase = (kc + 1) * 32;
            if (kbase < 192) {
#pragma unroll
                for (int i = 0; i < 4; i++) {
                    int off = i * 1024 + tid * 4;
                    pre[i] = *(const float4*)(nw1 + (kbase + (off >> 7)) * HD + (off & 127));
                }
            }
        }
        const float* ap = s_buf + (kc * 32) * STRIDE + ty * 8;
#pragma unroll 8
        for (int kk = 0; kk < 32; kk++) {
            float4 a0 = *(const float4*)(ap);
            float4 a1 = *(const float4*)(ap + 4);
            ap += STRIDE;
            ulonglong2 bA = *(const ulonglong2*)(s_w + kk * HD + 4 * tx);
            ulonglong2 bB = *(const ulonglong2*)(s_w + kk * HD + 64 + 4 * tx);
            float av[8] = {a0.x, a0.y, a0.z, a0.w, a1.x, a1.y, a1.z, a1.w};
#pragma unroll
            for (int r = 0; r < 8; r++) {
                u64 ar = pack2(av[r]);
                FMA2(acc[r][0], ar, bA.x);
                FMA2(acc[r][1], ar, bA.y);
                FMA2(acc[r][2], ar, bB.x);
                FMA2(acc[r][3], ar, bB.y);
            }
        }
    }
    __syncthreads();

    // stage A part 2: m_i k 64..127
#pragma unroll
    for (int it = 0; it < 8; it++) {
        int idx = it * 256 + tid;
        int kq = idx & 15, t = (idx >> 4) & 3, nl = idx >> 6;
        int node = n0 + nl; if (node >= N) node = N - 1;
        float4 v = *(const float4*)(g_mi + ((size_t)node * T + t) * HD + 64 + kq * 4);
        s_buf[(kq * 4 + 0) * STRIDE + nl * 4 + t] = v.x;
        s_buf[(kq * 4 + 1) * STRIDE + nl * 4 + t] = v.y;
        s_buf[(kq * 4 + 2) * STRIDE + nl * 4 + t] = v.z;
        s_buf[(kq * 4 + 3) * STRIDE + nl * 4 + t] = v.w;
    }
#pragma unroll 1
    for (int kc = 0; kc < 2; kc++) {
        __syncthreads();
#pragma unroll
        for (int i = 0; i < 4; i++)
            *(float4*)(s_w + i * 1024 + tid * 4) = pre[i];
        __syncthreads();
        if (kc == 0) {
#pragma unroll
            for (int i = 0; i < 4; i++) {
                int off = i * 1024 + tid * 4;
                pre[i] = *(const float4*)(nw1 + (160 + (off >> 7)) * HD + (off & 127));
            }
        }
        const float* ap = s_buf + (kc * 32) * STRIDE + ty * 8;
#pragma unroll 8
        for (int kk = 0; kk < 32; kk++) {
            float4 a0 = *(const float4*)(ap);
            float4 a1 = *(const float4*)(ap + 4);
            ap += STRIDE;
            ulonglong2 bA = *(const ulonglong2*)(s_w + kk * HD + 4 * tx);
            ulonglong2 bB = *(const ulonglong2*)(s_w + kk * HD + 64 + 4 * tx);
            float av[8] = {a0.x, a0.y, a0.z, a0.w, a1.x, a1.y, a1.z, a1.w};
#pragma unroll
            for (int r = 0; r < 8; r++) {
                u64 ar = pack2(av[r]);
                FMA2(acc[r][0], ar, bA.x);
                FMA2(acc[r][1], ar, bA.y);
                FMA2(acc[r][2], ar, bB.x);
                FMA2(acc[r][3], ar, bB.y);
            }
        }
    }

    float o1[8][8];
#pragma unroll
    for (int r = 0; r < 8; r++)
#pragma unroll
        for (int cp = 0; cp < 4; cp++) {
            float lo, hi; unpack2(acc[r][cp], lo, hi);
            o1[r][2 * cp]     = silu_f(lo);
            o1[r][2 * cp + 1] = silu_f(hi);
        }
    __syncthreads();
#pragma unroll
    for (int c = 0; c < 8; c++) {
        int col = (c < 4) ? 4 * tx + c : 60 + 4 * tx + c;
        *(float4*)(s_buf + col * STRIDE + ty * 8) =
            make_float4(o1[0][c], o1[1][c], o1[2][c], o1[3][c]);
        *(float4*)(s_buf + col * STRIDE + ty * 8 + 4) =
            make_float4(o1[4][c], o1[5][c], o1[6][c], o1[7][c]);
    }

    u64 acc2[8][2];
    {
        float4 b = *(const float4*)(nb2 + 4 * tx);
        u64 i0 = packab(b.x, b.y), i1 = packab(b.z, b.w);
#pragma unroll
        for (int r = 0; r < 8; r++) { acc2[r][0] = i0; acc2[r][1] = i1; }
    }
    float4 pre2[2];
#pragma unroll
    for (int i = 0; i < 2; i++) {
        int off = i * 1024 + tid * 4;
        pre2[i] = *(const float4*)(nw2 + (off >> 6) * HH + (off & 63));
    }
#pragma unroll 1
    for (int kc = 0; kc < 4; kc++) {
        __syncthreads();
#pragma unroll
        for (int i = 0; i < 2; i++)
            *(float4*)(s_w + i * 1024 + tid * 4) = pre2[i];
        __syncthreads();
        if (kc < 3) {
#pragma unroll
            for (int i = 0; i < 2; i++) {
                int off = i * 1024 + tid * 4;
                pre2[i] = *(const float4*)(nw2 + ((kc + 1) * 32 + (off >> 6)) * HH + (off & 63));
            }
        }
        const float* ap = s_buf + (kc * 32) * STRIDE + ty * 8;
#pragma unroll 8
        for (int kk = 0; kk < 32; kk++) {
            float4 a0 = *(const float4*)(ap);
            float4 a1 = *(const float4*)(ap + 4);
            ap += STRIDE;
            ulonglong2 w01 = *(const ulonglong2*)(s_w + kk * HH + 4 * tx);
            float av[8] = {a0.x, a0.y, a0.z, a0.w, a1.x, a1.y, a1.z, a1.w};
#pragma unroll
            for (int r = 0; r < 8; r++) {
                u64 ar = pack2(av[r]);
                FMA2(acc2[r][0], ar, w01.x);
                FMA2(acc2[r][1], ar, w01.y);
            }
        }
    }
    float o2[8][4];
#pragma unroll
    for (int r = 0; r < 8; r++) {
        unpack2(acc2[r][0], o2[r][0], o2[r][1]);
        unpack2(acc2[r][1], o2[r][2], o2[r][3]);
    }
#pragma unroll
    for (int half = 0; half < 2; half++) {
        int n = n0 + 2 * ty + half;
        if (n < N) {
#pragma unroll
            for (int c = 0; c < 4; c++) {
                int col = 4 * tx + c;
                *(float4*)(out_h + ((size_t)n * HH + col) * T) =
                    make_float4(o2[half * 4 + 0][c], o2[half * 4 + 1][c],
                                o2[half * 4 + 2][c], o2[half * 4 + 3][c]);
            }
        }
    }
}

extern "C" void kernel_launch(void* const* d_in, const int* in_sizes, int n_in,
                              void* d_out, int out_size)
{
    const float* x   = (const float*)d_in[0];
    const float* h   = (const float*)d_in[1];
    const int*   ei  = (const int*)  d_in[2];
    const float* ea  = (const float*)d_in[3];
    const float* ew1 = (const float*)d_in[5];
    const float* eb1 = (const float*)d_in[6];
    const float* ew2 = (const float*)d_in[7];
    const float* eb2 = (const float*)d_in[8];
    const float* cw1 = (const float*)d_in[9];
    const float* cb1 = (const float*)d_in[10];
    const float* cw2 = (const float*)d_in[11];
    const float* cb2 = (const float*)d_in[12];
    const float* nw1 = (const float*)d_in[13];
    const float* nb1 = (const float*)d_in[14];
    const float* nw2 = (const float*)d_in[15];
    const float* nb2 = (const float*)d_in[16];

    int N = in_sizes[0] / (3 * T);
    int E = in_sizes[3] / (HE * T);

    float* out_x = (float*)d_out;
    float* out_h = out_x + (size_t)N * 3 * T;

    const int pre_smem  = (HH * STRIDE + 32 * HD) * sizeof(float);
    const int node_smem = (HD * STRIDE + 32 * HD) * sizeof(float);
    const int edge_smem = 157952;
    cudaFuncSetAttribute(pre_kernel,  cudaFuncAttributeMaxDynamicSharedMemorySize, pre_smem);
    cudaFuncSetAttribute(node_kernel, cudaFuncAttributeMaxDynamicSharedMemorySize, node_smem);
    cudaFuncSetAttribute(edge_kernel, cudaFuncAttributeMaxDynamicSharedMemorySize, edge_smem);

    zero_kernel<<<2048, 256>>>(N);
    wimg_kernel<<<(HD * HD) / 256, 256>>>(ew2, cw1);
    pre_kernel<<<(N + NPRE - 1) / NPRE, 256, pre_smem>>>(h, ew1, N);
    edge_kernel<<<(E + EPB - 1) / EPB, 256, edge_smem>>>(
        x, ei, ea, ew1, eb1, eb2, cb1, cw2, cb2, E);
    node_kernel<<<(N + NPB - 1) / NPB, 256, node_smem>>>(
        x, h, nw1, nb1, nw2, nb2, out_x, out_h, N);
}